// round 1
// baseline (speedup 1.0000x reference)
#include <cuda_runtime.h>
#include <math.h>

#define BB 4
#define NN 512
#define DIM 512
#define HEADS 8
#define DH 64
#define DEPTH 4
#define ROWS (BB*NN)          // 2048
#define ATT_SCALE 0.125f      // 1/sqrt(64)
#define LN_EPS 1e-5f

// ---------------- scratch (static device memory; no allocation) -------------
__device__ float g_x_r [ROWS*DIM];
__device__ float g_x_i [ROWS*DIM];
__device__ float g_xn_r[ROWS*DIM];
__device__ float g_xn_i[ROWS*DIM];
__device__ float g_w_r [ROWS*DIM];
__device__ float g_w_i [ROWS*DIM];
__device__ float g_at_r[ROWS*DIM];
__device__ float g_at_i[ROWS*DIM];
__device__ float g_d_r [BB*HEADS*NN*NN];
__device__ float g_d_i [BB*HEADS*NN*NN];

// ---------------- small helpers --------------------------------------------
__device__ __forceinline__ float warp_sum(float v){
    #pragma unroll
    for (int o=16;o;o>>=1) v += __shfl_xor_sync(0xffffffffu, v, o);
    return v;
}
__device__ __forceinline__ float warp_max(float v){
    #pragma unroll
    for (int o=16;o;o>>=1) v = fmaxf(v, __shfl_xor_sync(0xffffffffu, v, o));
    return v;
}

// ---------------- copy in / out ---------------------------------------------
__global__ void copy_in_kernel(const float* __restrict__ a, const float* __restrict__ b,
                               float* __restrict__ xr, float* __restrict__ xi, int n){
    int i = blockIdx.x*blockDim.x + threadIdx.x;
    if (i < n){ xr[i] = a[i]; xi[i] = b[i]; }
}
__global__ void copy_out_kernel(const float* __restrict__ xr, const float* __restrict__ xi,
                                float* __restrict__ out, int n){
    int i = blockIdx.x*blockDim.x + threadIdx.x;
    if (i < n){ out[i] = xr[i]; out[n+i] = xi[i]; }
}

// ---------------- complex LayerNorm (per row of 512) ------------------------
__global__ __launch_bounds__(128)
void cln_kernel(const float* __restrict__ xr, const float* __restrict__ xi,
                const float* __restrict__ gr, const float* __restrict__ br,
                const float* __restrict__ gi, const float* __restrict__ bi,
                float* __restrict__ outr, float* __restrict__ outi)
{
    const int row = blockIdx.x;
    const int t   = threadIdx.x;          // 128 threads, 4 elems each
    const float4 vr = reinterpret_cast<const float4*>(xr + (size_t)row*DIM)[t];
    const float4 vi = reinterpret_cast<const float4*>(xi + (size_t)row*DIM)[t];

    float sr  = vr.x+vr.y+vr.z+vr.w;
    float s2r = vr.x*vr.x+vr.y*vr.y+vr.z*vr.z+vr.w*vr.w;
    float si  = vi.x+vi.y+vi.z+vi.w;
    float s2i = vi.x*vi.x+vi.y*vi.y+vi.z*vi.z+vi.w*vi.w;

    sr = warp_sum(sr); s2r = warp_sum(s2r); si = warp_sum(si); s2i = warp_sum(s2i);

    __shared__ float red[4][4];
    const int wid = t >> 5, lane = t & 31;
    if (lane == 0){ red[wid][0]=sr; red[wid][1]=s2r; red[wid][2]=si; red[wid][3]=s2i; }
    __syncthreads();
    float tr=0,t2r=0,ti=0,t2i=0;
    #pragma unroll
    for (int w=0; w<4; w++){ tr+=red[w][0]; t2r+=red[w][1]; ti+=red[w][2]; t2i+=red[w][3]; }

    const float inv = 1.0f/DIM;
    const float mr = tr*inv,  vvr = t2r*inv - mr*mr;
    const float mi = ti*inv,  vvi = t2i*inv - mi*mi;
    const float rr = rsqrtf(vvr + LN_EPS);
    const float ri = rsqrtf(vvi + LN_EPS);

    const float4 g4r = reinterpret_cast<const float4*>(gr)[t];
    const float4 b4r = reinterpret_cast<const float4*>(br)[t];
    const float4 g4i = reinterpret_cast<const float4*>(gi)[t];
    const float4 b4i = reinterpret_cast<const float4*>(bi)[t];

    float4 orr, oii;
    orr.x = (vr.x-mr)*rr*g4r.x + b4r.x;  oii.x = (vi.x-mi)*ri*g4i.x + b4i.x;
    orr.y = (vr.y-mr)*rr*g4r.y + b4r.y;  oii.y = (vi.y-mi)*ri*g4i.y + b4i.y;
    orr.z = (vr.z-mr)*rr*g4r.z + b4r.z;  oii.z = (vi.z-mi)*ri*g4i.z + b4i.z;
    orr.w = (vr.w-mr)*rr*g4r.w + b4r.w;  oii.w = (vi.w-mi)*ri*g4i.w + b4i.w;
    reinterpret_cast<float4*>(outr + (size_t)row*DIM)[t] = orr;
    reinterpret_cast<float4*>(outi + (size_t)row*DIM)[t] = oii;
}

// ---------------- magnitude softmax, phase preserved, in place --------------
__global__ __launch_bounds__(256)
void csoftmax_kernel(float* __restrict__ zr, float* __restrict__ zi)
{
    const size_t row = blockIdx.x;
    float* pr = zr + row*NN;
    float* pi = zi + row*NN;
    const int t = threadIdx.x;                 // 256 threads, 2 elems each
    const float2 vr = *reinterpret_cast<const float2*>(pr + 2*t);
    const float2 vi = *reinterpret_cast<const float2*>(pi + 2*t);
    const float m0 = sqrtf(vr.x*vr.x + vi.x*vi.x);
    const float m1 = sqrtf(vr.y*vr.y + vi.y*vi.y);

    __shared__ float smax[8];
    __shared__ float ssum[8];
    const int wid = t >> 5, lane = t & 31;

    float mx = warp_max(fmaxf(m0, m1));
    if (lane == 0) smax[wid] = mx;
    __syncthreads();
    float bmax = smax[0];
    #pragma unroll
    for (int i=1;i<8;i++) bmax = fmaxf(bmax, smax[i]);

    const float e0 = expf(m0 - bmax);
    const float e1 = expf(m1 - bmax);
    float s = warp_sum(e0 + e1);
    if (lane == 0) ssum[wid] = s;
    __syncthreads();
    float bsum = 0.f;
    #pragma unroll
    for (int i=0;i<8;i++) bsum += ssum[i];
    const float inv = 1.0f / bsum;
    const float p0 = e0*inv, p1 = e1*inv;

    float2 orr, oii;
    if (m0 > 0.f){ const float s0 = p0/m0; orr.x = vr.x*s0; oii.x = vi.x*s0; }
    else         { orr.x = p0; oii.x = 0.f; }
    if (m1 > 0.f){ const float s1 = p1/m1; orr.y = vr.y*s1; oii.y = vi.y*s1; }
    else         { orr.y = p1; oii.y = 0.f; }
    *reinterpret_cast<float2*>(pr + 2*t) = orr;
    *reinterpret_cast<float2*>(pi + 2*t) = oii;
}

// ---------------- complex GEMM, NT: C[m,n] = sum_k A[m,k] * (conj?)B[n,k] ----
// 64x64 tile, BK=16, 256 threads, 4x4 complex per thread.
// EPI 0: C = alpha*acc
// EPI 1: C = acc + bias[n] + C        (out-proj + residual; C holds old x)
// EPI 2: C = crelu(X[m,n] + ss*acc - ss*lm_realpart)   (ISTA FF; X = xn)
template<int EPI, bool CONJB>
__global__ __launch_bounds__(256)
void cgemm_nt_kernel(const float* __restrict__ Ar, const float* __restrict__ Ai, int lda,
                     const float* __restrict__ Br, const float* __restrict__ Bi, int ldb,
                     float* Cr, float* Ci, int ldc,
                     int K, float alpha,
                     size_t sAb, size_t sAh, size_t sBb, size_t sBh,
                     size_t sCb, size_t sCh,
                     const float* __restrict__ biasR, const float* __restrict__ biasI,
                     const float* __restrict__ Xr, const float* __restrict__ Xi,
                     const float* __restrict__ ssp, const float* __restrict__ lmp, int layer)
{
    const int zb = blockIdx.z >> 3, zh = blockIdx.z & 7;
    const size_t Aoff = (size_t)zb*sAb + (size_t)zh*sAh;
    const size_t Boff = (size_t)zb*sBb + (size_t)zh*sBh;
    const size_t Coff = (size_t)zb*sCb + (size_t)zh*sCh;

    const int m0 = blockIdx.y * 64;
    const int n0 = blockIdx.x * 64;

    __shared__ float As_r[16][64], As_i[16][64], Bs_r[16][64], Bs_i[16][64];

    const int tid = threadIdx.x;
    const int tx = tid & 15, ty = tid >> 4;
    const int lr = tid >> 2;             // 0..63 row within tile
    const int lk = (tid & 3) << 2;       // 0,4,8,12

    const float* pAr = Ar + Aoff + (size_t)(m0+lr)*lda + lk;
    const float* pAi = Ai + Aoff + (size_t)(m0+lr)*lda + lk;
    const float* pBr = Br + Boff + (size_t)(n0+lr)*ldb + lk;
    const float* pBi = Bi + Boff + (size_t)(n0+lr)*ldb + lk;

    float cr[4][4] = {}, ci[4][4] = {};

    for (int k0 = 0; k0 < K; k0 += 16){
        const float4 va = *reinterpret_cast<const float4*>(pAr + k0);
        const float4 vb = *reinterpret_cast<const float4*>(pAi + k0);
        const float4 vc = *reinterpret_cast<const float4*>(pBr + k0);
        const float4 vd = *reinterpret_cast<const float4*>(pBi + k0);
        As_r[lk+0][lr]=va.x; As_r[lk+1][lr]=va.y; As_r[lk+2][lr]=va.z; As_r[lk+3][lr]=va.w;
        As_i[lk+0][lr]=vb.x; As_i[lk+1][lr]=vb.y; As_i[lk+2][lr]=vb.z; As_i[lk+3][lr]=vb.w;
        Bs_r[lk+0][lr]=vc.x; Bs_r[lk+1][lr]=vc.y; Bs_r[lk+2][lr]=vc.z; Bs_r[lk+3][lr]=vc.w;
        Bs_i[lk+0][lr]=vd.x; Bs_i[lk+1][lr]=vd.y; Bs_i[lk+2][lr]=vd.z; Bs_i[lk+3][lr]=vd.w;
        __syncthreads();
        #pragma unroll
        for (int kk = 0; kk < 16; kk++){
            const float4 a_r = *reinterpret_cast<const float4*>(&As_r[kk][ty<<2]);
            const float4 a_i = *reinterpret_cast<const float4*>(&As_i[kk][ty<<2]);
            const float4 b_r = *reinterpret_cast<const float4*>(&Bs_r[kk][tx<<2]);
            const float4 b_i = *reinterpret_cast<const float4*>(&Bs_i[kk][tx<<2]);
            const float arr[4] = {a_r.x,a_r.y,a_r.z,a_r.w};
            const float aii[4] = {a_i.x,a_i.y,a_i.z,a_i.w};
            const float brr[4] = {b_r.x,b_r.y,b_r.z,b_r.w};
            const float bii[4] = {b_i.x,b_i.y,b_i.z,b_i.w};
            #pragma unroll
            for (int i=0;i<4;i++){
                #pragma unroll
                for (int j=0;j<4;j++){
                    if (CONJB){
                        cr[i][j] = fmaf(arr[i], brr[j], cr[i][j]);
                        cr[i][j] = fmaf(aii[i], bii[j], cr[i][j]);
                        ci[i][j] = fmaf(aii[i], brr[j], ci[i][j]);
                        ci[i][j] = fmaf(-arr[i], bii[j], ci[i][j]);
                    } else {
                        cr[i][j] = fmaf(arr[i], brr[j], cr[i][j]);
                        cr[i][j] = fmaf(-aii[i], bii[j], cr[i][j]);
                        ci[i][j] = fmaf(arr[i], bii[j], ci[i][j]);
                        ci[i][j] = fmaf(aii[i], brr[j], ci[i][j]);
                    }
                }
            }
        }
        __syncthreads();
    }

    float ss = 0.f, lm = 0.f;
    if (EPI == 2){
        ss = log1pf(expf(ssp[layer]));
        lm = log1pf(expf(lmp[layer]));
    }

    #pragma unroll
    for (int i=0;i<4;i++){
        const int gm = m0 + (ty<<2) + i;
        #pragma unroll
        for (int j=0;j<4;j++){
            const int gn = n0 + (tx<<2) + j;
            const size_t idx = Coff + (size_t)gm*ldc + gn;
            const float vr = cr[i][j]*alpha;
            const float vi = ci[i][j]*alpha;
            if (EPI == 0){
                Cr[idx] = vr; Ci[idx] = vi;
            } else if (EPI == 1){
                Cr[idx] = vr + biasR[gn] + Cr[idx];
                Ci[idx] = vi + biasI[gn] + Ci[idx];
            } else {
                const float xnr = Xr[(size_t)gm*ldc + gn];
                const float xni = Xi[(size_t)gm*ldc + gn];
                Cr[idx] = fmaxf(fmaf(ss, vr, xnr) - ss*lm, 0.f);
                Ci[idx] = fmaxf(fmaf(ss, vi, xni), 0.f);
            }
        }
    }
}

// ---------------- complex GEMM, NN: C[m,n] = sum_k A[m,k]*B[k,n] ------------
__global__ __launch_bounds__(256)
void cgemm_nn_kernel(const float* __restrict__ Ar, const float* __restrict__ Ai, int lda,
                     const float* __restrict__ Br, const float* __restrict__ Bi, int ldb,
                     float* __restrict__ Cr, float* __restrict__ Ci, int ldc,
                     int K,
                     size_t sAb, size_t sAh, size_t sBb, size_t sBh,
                     size_t sCb, size_t sCh)
{
    const int zb = blockIdx.z >> 3, zh = blockIdx.z & 7;
    const size_t Aoff = (size_t)zb*sAb + (size_t)zh*sAh;
    const size_t Boff = (size_t)zb*sBb + (size_t)zh*sBh;
    const size_t Coff = (size_t)zb*sCb + (size_t)zh*sCh;

    const int m0 = blockIdx.y * 64;
    const int n0 = blockIdx.x * 64;

    __shared__ float As_r[16][64], As_i[16][64], Bs_r[16][64], Bs_i[16][64];

    const int tid = threadIdx.x;
    const int tx = tid & 15, ty = tid >> 4;
    const int lr = tid >> 2;
    const int lk = (tid & 3) << 2;
    const int kb = tid >> 4;             // 0..15  (B tile row = k)
    const int nc = (tid & 15) << 2;      // 0..60  (B tile col)

    const float* pAr = Ar + Aoff + (size_t)(m0+lr)*lda + lk;
    const float* pAi = Ai + Aoff + (size_t)(m0+lr)*lda + lk;
    const float* pBr = Br + Boff + n0 + nc;
    const float* pBi = Bi + Boff + n0 + nc;

    float cr[4][4] = {}, ci[4][4] = {};

    for (int k0 = 0; k0 < K; k0 += 16){
        const float4 va = *reinterpret_cast<const float4*>(pAr + k0);
        const float4 vb = *reinterpret_cast<const float4*>(pAi + k0);
        const float4 vc = *reinterpret_cast<const float4*>(pBr + (size_t)(k0+kb)*ldb);
        const float4 vd = *reinterpret_cast<const float4*>(pBi + (size_t)(k0+kb)*ldb);
        As_r[lk+0][lr]=va.x; As_r[lk+1][lr]=va.y; As_r[lk+2][lr]=va.z; As_r[lk+3][lr]=va.w;
        As_i[lk+0][lr]=vb.x; As_i[lk+1][lr]=vb.y; As_i[lk+2][lr]=vb.z; As_i[lk+3][lr]=vb.w;
        *reinterpret_cast<float4*>(&Bs_r[kb][nc]) = vc;
        *reinterpret_cast<float4*>(&Bs_i[kb][nc]) = vd;
        __syncthreads();
        #pragma unroll
        for (int kk = 0; kk < 16; kk++){
            const float4 a_r = *reinterpret_cast<const float4*>(&As_r[kk][ty<<2]);
            const float4 a_i = *reinterpret_cast<const float4*>(&As_i[kk][ty<<2]);
            const float4 b_r = *reinterpret_cast<const float4*>(&Bs_r[kk][tx<<2]);
            const float4 b_i = *reinterpret_cast<const float4*>(&Bs_i[kk][tx<<2]);
            const float arr[4] = {a_r.x,a_r.y,a_r.z,a_r.w};
            const float aii[4] = {a_i.x,a_i.y,a_i.z,a_i.w};
            const float brr[4] = {b_r.x,b_r.y,b_r.z,b_r.w};
            const float bii[4] = {b_i.x,b_i.y,b_i.z,b_i.w};
            #pragma unroll
            for (int i=0;i<4;i++){
                #pragma unroll
                for (int j=0;j<4;j++){
                    cr[i][j] = fmaf(arr[i], brr[j], cr[i][j]);
                    cr[i][j] = fmaf(-aii[i], bii[j], cr[i][j]);
                    ci[i][j] = fmaf(arr[i], bii[j], ci[i][j]);
                    ci[i][j] = fmaf(aii[i], brr[j], ci[i][j]);
                }
            }
        }
        __syncthreads();
    }

    #pragma unroll
    for (int i=0;i<4;i++){
        const int gm = m0 + (ty<<2) + i;
        #pragma unroll
        for (int j=0;j<4;j++){
            const int gn = n0 + (tx<<2) + j;
            const size_t idx = Coff + (size_t)gm*ldc + gn;
            Cr[idx] = cr[i][j];
            Ci[idx] = ci[i][j];
        }
    }
}

// ---------------- launch ----------------------------------------------------
extern "C" void kernel_launch(void* const* d_in, const int* in_sizes, int n_in,
                              void* d_out, int out_size)
{
    const float* x_real   = (const float*)d_in[0];
    const float* x_imag   = (const float*)d_in[1];
    const float* ln1_g_r  = (const float*)d_in[2];
    const float* ln1_b_r  = (const float*)d_in[3];
    const float* ln1_g_i  = (const float*)d_in[4];
    const float* ln1_b_i  = (const float*)d_in[5];
    const float* ln2_g_r  = (const float*)d_in[6];
    const float* ln2_b_r  = (const float*)d_in[7];
    const float* ln2_g_i  = (const float*)d_in[8];
    const float* ln2_b_i  = (const float*)d_in[9];
    const float* qkv_w_r  = (const float*)d_in[10];
    const float* qkv_w_i  = (const float*)d_in[11];
    const float* out_w_r  = (const float*)d_in[12];
    const float* out_w_i  = (const float*)d_in[13];
    const float* out_b_r  = (const float*)d_in[14];
    const float* out_b_i  = (const float*)d_in[15];
    const float* ff_w_r   = (const float*)d_in[16];
    const float* ff_w_i   = (const float*)d_in[17];
    const float* step_sz  = (const float*)d_in[18];
    const float* lambd    = (const float*)d_in[19];

    float *xr,*xi,*xnr,*xni,*wr,*wi,*ar,*ai,*dr,*di;
    cudaGetSymbolAddress((void**)&xr,  g_x_r);
    cudaGetSymbolAddress((void**)&xi,  g_x_i);
    cudaGetSymbolAddress((void**)&xnr, g_xn_r);
    cudaGetSymbolAddress((void**)&xni, g_xn_i);
    cudaGetSymbolAddress((void**)&wr,  g_w_r);
    cudaGetSymbolAddress((void**)&wi,  g_w_i);
    cudaGetSymbolAddress((void**)&ar,  g_at_r);
    cudaGetSymbolAddress((void**)&ai,  g_at_i);
    cudaGetSymbolAddress((void**)&dr,  g_d_r);
    cudaGetSymbolAddress((void**)&di,  g_d_i);

    const int NE = ROWS*DIM;             // 1,048,576
    copy_in_kernel<<<(NE+255)/256, 256>>>(x_real, x_imag, xr, xi, NE);

    const size_t sRow = (size_t)NN*DIM;      // per-batch row-block stride (262144)
    const size_t sNN  = (size_t)NN*NN;       // per-(b,h) dots stride (262144)

    for (int l = 0; l < DEPTH; l++){
        const size_t wo = (size_t)l*DIM*DIM;
        const size_t po = (size_t)l*DIM;

        // LN1
        cln_kernel<<<ROWS,128>>>(xr,xi, ln1_g_r+po, ln1_b_r+po, ln1_g_i+po, ln1_b_i+po, xnr,xni);
        // QKV: w = xn @ Wqkv^T
        cgemm_nt_kernel<0,false><<<dim3(8,32,1),256>>>(
            xnr,xni,DIM, qkv_w_r+wo,qkv_w_i+wo,DIM, wr,wi,DIM, DIM, 1.0f,
            0,0,0,0,0,0, nullptr,nullptr, nullptr,nullptr, nullptr,nullptr, 0);
        // dots[b,h] = scale * w @ conj(w)^T  (K = 64)
        cgemm_nt_kernel<0,true><<<dim3(8,8,32),256>>>(
            wr,wi,DIM, wr,wi,DIM, dr,di,NN, DH, ATT_SCALE,
            sRow,(size_t)DH, sRow,(size_t)DH, (size_t)8*sNN, sNN,
            nullptr,nullptr, nullptr,nullptr, nullptr,nullptr, 0);
        // magnitude softmax, phase preserved
        csoftmax_kernel<<<BB*HEADS*NN,256>>>(dr,di);
        // att = attn @ w  (per (b,h), M=512, N=64, K=512)
        cgemm_nn_kernel<<<dim3(1,8,32),256>>>(
            dr,di,NN, wr,wi,DIM, ar,ai,DIM, NN,
            (size_t)8*sNN, sNN, sRow,(size_t)DH, sRow,(size_t)DH);
        // x = att @ Wout^T + bout + x
        cgemm_nt_kernel<1,false><<<dim3(8,32,1),256>>>(
            ar,ai,DIM, out_w_r+wo,out_w_i+wo,DIM, xr,xi,DIM, DIM, 1.0f,
            0,0,0,0,0,0, out_b_r+po,out_b_i+po, nullptr,nullptr, nullptr,nullptr, 0);
        // LN2
        cln_kernel<<<ROWS,128>>>(xr,xi, ln2_g_r+po, ln2_b_r+po, ln2_g_i+po, ln2_b_i+po, xnr,xni);
        // x = crelu(xn + ss*(xn @ Wff^T) - ss*lm)
        cgemm_nt_kernel<2,false><<<dim3(8,32,1),256>>>(
            xnr,xni,DIM, ff_w_r+wo,ff_w_i+wo,DIM, xr,xi,DIM, DIM, 1.0f,
            0,0,0,0,0,0, nullptr,nullptr, xnr,xni, step_sz,lambd, l);
    }

    copy_out_kernel<<<(NE+255)/256, 256>>>(xr, xi, (float*)d_out, NE);
}

// round 2
// speedup vs baseline: 1.0618x; 1.0618x over previous
#include <cuda_runtime.h>
#include <math.h>

#define BB 4
#define NN 512
#define DIM 512
#define HEADS 8
#define DH 64
#define DEPTH 4
#define ROWS (BB*NN)          // 2048
#define ATT_SCALE 0.125f
#define LN_EPS 1e-5f

// ---------------- scratch (static device memory; no allocation) -------------
__device__ float g_x_r [ROWS*DIM];
__device__ float g_x_i [ROWS*DIM];
__device__ float g_xn_r[ROWS*DIM];
__device__ float g_xn_i[ROWS*DIM];
__device__ float g_w_r [ROWS*DIM];
__device__ float g_w_i [ROWS*DIM];
__device__ float g_at_r[ROWS*DIM];
__device__ float g_at_i[ROWS*DIM];
__device__ float g_d_r [BB*HEADS*NN*NN];
__device__ float g_d_i [BB*HEADS*NN*NN];

// ---------------- f32x2 helpers ---------------------------------------------
typedef unsigned long long u64t;

__device__ __forceinline__ u64t dup2(float s){
    u64t r; asm("mov.b64 %0, {%1, %1};" : "=l"(r) : "f"(s)); return r;
}
__device__ __forceinline__ void fma2(u64t &d, u64t a, u64t b){
    asm("fma.rn.f32x2 %0, %1, %2, %0;" : "+l"(d) : "l"(a), "l"(b));
}
__device__ __forceinline__ void lds2x64(u64t &a, u64t &b, unsigned addr){
    asm volatile("ld.shared.v2.b64 {%0, %1}, [%2];" : "=l"(a), "=l"(b) : "r"(addr));
}
__device__ __forceinline__ float2 up2(u64t v){
    float2 f; asm("mov.b64 {%0, %1}, %2;" : "=f"(f.x), "=f"(f.y) : "l"(v)); return f;
}

__device__ __forceinline__ float warp_sum(float v){
    #pragma unroll
    for (int o=16;o;o>>=1) v += __shfl_xor_sync(0xffffffffu, v, o);
    return v;
}
__device__ __forceinline__ float warp_max(float v){
    #pragma unroll
    for (int o=16;o;o>>=1) v = fmaxf(v, __shfl_xor_sync(0xffffffffu, v, o));
    return v;
}

// ---------------- copy in / out ---------------------------------------------
__global__ void copy_in_kernel(const float* __restrict__ a, const float* __restrict__ b,
                               float* __restrict__ xr, float* __restrict__ xi, int n){
    int i = blockIdx.x*blockDim.x + threadIdx.x;
    if (i < n){ xr[i] = a[i]; xi[i] = b[i]; }
}
__global__ void copy_out_kernel(const float* __restrict__ xr, const float* __restrict__ xi,
                                float* __restrict__ out, int n){
    int i = blockIdx.x*blockDim.x + threadIdx.x;
    if (i < n){ out[i] = xr[i]; out[n+i] = xi[i]; }
}

// ---------------- complex LayerNorm (per row of 512) ------------------------
__global__ __launch_bounds__(128)
void cln_kernel(const float* __restrict__ xr, const float* __restrict__ xi,
                const float* __restrict__ gr, const float* __restrict__ br,
                const float* __restrict__ gi, const float* __restrict__ bi,
                float* __restrict__ outr, float* __restrict__ outi)
{
    const int row = blockIdx.x;
    const int t   = threadIdx.x;
    const float4 vr = reinterpret_cast<const float4*>(xr + (size_t)row*DIM)[t];
    const float4 vi = reinterpret_cast<const float4*>(xi + (size_t)row*DIM)[t];

    float sr  = vr.x+vr.y+vr.z+vr.w;
    float s2r = vr.x*vr.x+vr.y*vr.y+vr.z*vr.z+vr.w*vr.w;
    float si  = vi.x+vi.y+vi.z+vi.w;
    float s2i = vi.x*vi.x+vi.y*vi.y+vi.z*vi.z+vi.w*vi.w;

    sr = warp_sum(sr); s2r = warp_sum(s2r); si = warp_sum(si); s2i = warp_sum(s2i);

    __shared__ float red[4][4];
    const int wid = t >> 5, lane = t & 31;
    if (lane == 0){ red[wid][0]=sr; red[wid][1]=s2r; red[wid][2]=si; red[wid][3]=s2i; }
    __syncthreads();
    float tr=0,t2r=0,ti=0,t2i=0;
    #pragma unroll
    for (int w=0; w<4; w++){ tr+=red[w][0]; t2r+=red[w][1]; ti+=red[w][2]; t2i+=red[w][3]; }

    const float inv = 1.0f/DIM;
    const float mr = tr*inv,  vvr = t2r*inv - mr*mr;
    const float mi = ti*inv,  vvi = t2i*inv - mi*mi;
    const float rr = rsqrtf(vvr + LN_EPS);
    const float ri = rsqrtf(vvi + LN_EPS);

    const float4 g4r = reinterpret_cast<const float4*>(gr)[t];
    const float4 b4r = reinterpret_cast<const float4*>(br)[t];
    const float4 g4i = reinterpret_cast<const float4*>(gi)[t];
    const float4 b4i = reinterpret_cast<const float4*>(bi)[t];

    float4 orr, oii;
    orr.x = (vr.x-mr)*rr*g4r.x + b4r.x;  oii.x = (vi.x-mi)*ri*g4i.x + b4i.x;
    orr.y = (vr.y-mr)*rr*g4r.y + b4r.y;  oii.y = (vi.y-mi)*ri*g4i.y + b4i.y;
    orr.z = (vr.z-mr)*rr*g4r.z + b4r.z;  oii.z = (vi.z-mi)*ri*g4i.z + b4i.z;
    orr.w = (vr.w-mr)*rr*g4r.w + b4r.w;  oii.w = (vi.w-mi)*ri*g4i.w + b4i.w;
    reinterpret_cast<float4*>(outr + (size_t)row*DIM)[t] = orr;
    reinterpret_cast<float4*>(outi + (size_t)row*DIM)[t] = oii;
}

// ---------------- magnitude softmax, phase preserved, in place --------------
__global__ __launch_bounds__(256)
void csoftmax_kernel(float* __restrict__ zr, float* __restrict__ zi)
{
    const size_t row = blockIdx.x;
    float* pr = zr + row*NN;
    float* pi = zi + row*NN;
    const int t = threadIdx.x;
    const float2 vr = *reinterpret_cast<const float2*>(pr + 2*t);
    const float2 vi = *reinterpret_cast<const float2*>(pi + 2*t);
    const float m0 = sqrtf(vr.x*vr.x + vi.x*vi.x);
    const float m1 = sqrtf(vr.y*vr.y + vi.y*vi.y);

    __shared__ float smax[8];
    __shared__ float ssum[8];
    const int wid = t >> 5, lane = t & 31;

    float mx = warp_max(fmaxf(m0, m1));
    if (lane == 0) smax[wid] = mx;
    __syncthreads();
    float bmax = smax[0];
    #pragma unroll
    for (int i=1;i<8;i++) bmax = fmaxf(bmax, smax[i]);

    const float e0 = expf(m0 - bmax);
    const float e1 = expf(m1 - bmax);
    float s = warp_sum(e0 + e1);
    if (lane == 0) ssum[wid] = s;
    __syncthreads();
    float bsum = 0.f;
    #pragma unroll
    for (int i=0;i<8;i++) bsum += ssum[i];
    const float inv = 1.0f / bsum;
    const float p0 = e0*inv, p1 = e1*inv;

    float2 orr, oii;
    if (m0 > 0.f){ const float s0 = p0/m0; orr.x = vr.x*s0; oii.x = vi.x*s0; }
    else         { orr.x = p0; oii.x = 0.f; }
    if (m1 > 0.f){ const float s1 = p1/m1; orr.y = vr.y*s1; oii.y = vi.y*s1; }
    else         { orr.y = p1; oii.y = 0.f; }
    *reinterpret_cast<float2*>(pr + 2*t) = orr;
    *reinterpret_cast<float2*>(pi + 2*t) = oii;
}

// ======================= f32x2 complex GEMM =================================
// Tile: 128(M) x 64(N) complex, BK=16, 256 threads, per-thread 8x4 complex.
// Accumulator pairs packed along M. ty=tid>>4 (rows ty*8..+7), tx=tid&15 (cols tx*4..+3).

#define BM 128
#define BN 64
#define BK 16
#define APAD 132   // 128 + 4, row stride (floats) -> 528B, 16B aligned
#define BPAD 68    // 64 + 4  -> 272B, 16B aligned

// ---- NT: C[m,n] = alpha * sum_k A[m,k] * (conj?) B[n,k] --------------------
// EPI 0: C = alpha*acc
// EPI 1: C = acc + bias[n] + C
// EPI 2: C = crelu(X[m,n] + ss*acc - ss*lm (real only))
template<int EPI, bool CONJB>
__global__ __launch_bounds__(256, 2)
void cgemm_nt_kernel(const float* __restrict__ Ar, const float* __restrict__ Ai, int lda,
                     const float* __restrict__ Br, const float* __restrict__ Bi, int ldb,
                     float* Cr, float* Ci, int ldc,
                     int K, float alpha,
                     size_t sAb, size_t sAh, size_t sBb, size_t sBh,
                     size_t sCb, size_t sCh,
                     const float* __restrict__ biasR, const float* __restrict__ biasI,
                     const float* __restrict__ Xr, const float* __restrict__ Xi,
                     const float* __restrict__ ssp, const float* __restrict__ lmp, int layer)
{
    const int zb = blockIdx.z >> 3, zh = blockIdx.z & 7;
    const size_t Aoff = (size_t)zb*sAb + (size_t)zh*sAh;
    const size_t Boff = (size_t)zb*sBb + (size_t)zh*sBh;
    const size_t Coff = (size_t)zb*sCb + (size_t)zh*sCh;

    const int m0 = blockIdx.y * BM;
    const int n0 = blockIdx.x * BN;

    __shared__ float As_r[BK][APAD], As_i[BK][APAD], Bs_r[BK][BPAD], Bs_i[BK][BPAD];

    const int tid = threadIdx.x;
    const int tx = tid & 15, ty = tid >> 4;

    // loader mappings
    const int lrA = tid >> 2;            // 0..63 (rows lrA and lrA+64)
    const int lkA = (tid & 3) << 2;      // 0,4,8,12
    const int nB  = tid >> 2;            // 0..63
    const int lkB = (tid & 3) << 2;

    const float* pAr0 = Ar + Aoff + (size_t)(m0+lrA)*lda + lkA;
    const float* pAi0 = Ai + Aoff + (size_t)(m0+lrA)*lda + lkA;
    const float* pAr1 = pAr0 + (size_t)64*lda;
    const float* pAi1 = pAi0 + (size_t)64*lda;
    const float* pBr  = Br + Boff + (size_t)(n0+nB)*ldb + lkB;
    const float* pBi  = Bi + Boff + (size_t)(n0+nB)*ldb + lkB;

    const unsigned baseAr = (unsigned)__cvta_generic_to_shared(&As_r[0][0]) + ty*32;
    const unsigned baseAi = (unsigned)__cvta_generic_to_shared(&As_i[0][0]) + ty*32;

    u64t cr[4][4] = {}, ci[4][4] = {};

    for (int k0 = 0; k0 < K; k0 += BK){
        const float4 a0r = *reinterpret_cast<const float4*>(pAr0 + k0);
        const float4 a0i = *reinterpret_cast<const float4*>(pAi0 + k0);
        const float4 a1r = *reinterpret_cast<const float4*>(pAr1 + k0);
        const float4 a1i = *reinterpret_cast<const float4*>(pAi1 + k0);
        const float4 b0r = *reinterpret_cast<const float4*>(pBr  + k0);
        const float4 b0i = *reinterpret_cast<const float4*>(pBi  + k0);
        As_r[lkA+0][lrA]=a0r.x; As_r[lkA+1][lrA]=a0r.y; As_r[lkA+2][lrA]=a0r.z; As_r[lkA+3][lrA]=a0r.w;
        As_i[lkA+0][lrA]=a0i.x; As_i[lkA+1][lrA]=a0i.y; As_i[lkA+2][lrA]=a0i.z; As_i[lkA+3][lrA]=a0i.w;
        As_r[lkA+0][lrA+64]=a1r.x; As_r[lkA+1][lrA+64]=a1r.y; As_r[lkA+2][lrA+64]=a1r.z; As_r[lkA+3][lrA+64]=a1r.w;
        As_i[lkA+0][lrA+64]=a1i.x; As_i[lkA+1][lrA+64]=a1i.y; As_i[lkA+2][lrA+64]=a1i.z; As_i[lkA+3][lrA+64]=a1i.w;
        Bs_r[lkB+0][nB]=b0r.x; Bs_r[lkB+1][nB]=b0r.y; Bs_r[lkB+2][nB]=b0r.z; Bs_r[lkB+3][nB]=b0r.w;
        Bs_i[lkB+0][nB]=b0i.x; Bs_i[lkB+1][nB]=b0i.y; Bs_i[lkB+2][nB]=b0i.z; Bs_i[lkB+3][nB]=b0i.w;
        __syncthreads();

        #pragma unroll
        for (int kk = 0; kk < BK; kk++){
            u64t ar[4], ai[4];
            const unsigned offk = kk*(APAD*4);
            lds2x64(ar[0], ar[1], baseAr + offk);
            lds2x64(ar[2], ar[3], baseAr + offk + 16);
            lds2x64(ai[0], ai[1], baseAi + offk);
            lds2x64(ai[2], ai[3], baseAi + offk + 16);

            const float4 b4r = *reinterpret_cast<const float4*>(&Bs_r[kk][tx<<2]);
            const float4 b4i = *reinterpret_cast<const float4*>(&Bs_i[kk][tx<<2]);
            const float brr[4] = {b4r.x,b4r.y,b4r.z,b4r.w};
            const float bii[4] = {b4i.x,b4i.y,b4i.z,b4i.w};
            u64t brd[4], bid[4], nbid[4];
            #pragma unroll
            for (int j=0;j<4;j++){
                brd[j]  = dup2(brr[j]);
                bid[j]  = dup2(bii[j]);
                nbid[j] = dup2(-bii[j]);
            }
            #pragma unroll
            for (int ip=0;ip<4;ip++){
                #pragma unroll
                for (int j=0;j<4;j++){
                    if (CONJB){
                        fma2(cr[ip][j], ar[ip], brd[j]);
                        fma2(cr[ip][j], ai[ip], bid[j]);
                        fma2(ci[ip][j], ai[ip], brd[j]);
                        fma2(ci[ip][j], ar[ip], nbid[j]);
                    } else {
                        fma2(cr[ip][j], ar[ip], brd[j]);
                        fma2(cr[ip][j], ai[ip], nbid[j]);
                        fma2(ci[ip][j], ar[ip], bid[j]);
                        fma2(ci[ip][j], ai[ip], brd[j]);
                    }
                }
            }
        }
        __syncthreads();
    }

    float ss = 0.f, lm = 0.f;
    if (EPI == 2){
        ss = log1pf(expf(ssp[layer]));
        lm = log1pf(expf(lmp[layer]));
    }

    #pragma unroll
    for (int ip=0;ip<4;ip++){
        const int gm = m0 + ty*8 + ip*2;
        #pragma unroll
        for (int j=0;j<4;j++){
            const int gn = n0 + (tx<<2) + j;
            float2 vr = up2(cr[ip][j]);
            float2 vi = up2(ci[ip][j]);
            vr.x *= alpha; vr.y *= alpha; vi.x *= alpha; vi.y *= alpha;
            const size_t i0 = Coff + (size_t)gm*ldc + gn;
            const size_t i1 = i0 + ldc;
            if (EPI == 0){
                Cr[i0] = vr.x; Ci[i0] = vi.x;
                Cr[i1] = vr.y; Ci[i1] = vi.y;
            } else if (EPI == 1){
                Cr[i0] = vr.x + biasR[gn] + Cr[i0];
                Ci[i0] = vi.x + biasI[gn] + Ci[i0];
                Cr[i1] = vr.y + biasR[gn] + Cr[i1];
                Ci[i1] = vi.y + biasI[gn] + Ci[i1];
            } else {
                const float x0r = Xr[(size_t)gm*ldc + gn];
                const float x0i = Xi[(size_t)gm*ldc + gn];
                const float x1r = Xr[(size_t)(gm+1)*ldc + gn];
                const float x1i = Xi[(size_t)(gm+1)*ldc + gn];
                Cr[i0] = fmaxf(fmaf(ss, vr.x, x0r) - ss*lm, 0.f);
                Ci[i0] = fmaxf(fmaf(ss, vi.x, x0i), 0.f);
                Cr[i1] = fmaxf(fmaf(ss, vr.y, x1r) - ss*lm, 0.f);
                Ci[i1] = fmaxf(fmaf(ss, vi.y, x1i), 0.f);
            }
        }
    }
}

// ---- NN: C[m,n] = sum_k A[m,k] * B[k,n] ------------------------------------
__global__ __launch_bounds__(256, 2)
void cgemm_nn_kernel(const float* __restrict__ Ar, const float* __restrict__ Ai, int lda,
                     const float* __restrict__ Br, const float* __restrict__ Bi, int ldb,
                     float* __restrict__ Cr, float* __restrict__ Ci, int ldc,
                     int K,
                     size_t sAb, size_t sAh, size_t sBb, size_t sBh,
                     size_t sCb, size_t sCh)
{
    const int zb = blockIdx.z >> 3, zh = blockIdx.z & 7;
    const size_t Aoff = (size_t)zb*sAb + (size_t)zh*sAh;
    const size_t Boff = (size_t)zb*sBb + (size_t)zh*sBh;
    const size_t Coff = (size_t)zb*sCb + (size_t)zh*sCh;

    const int m0 = blockIdx.y * BM;
    const int n0 = blockIdx.x * BN;

    __shared__ float As_r[BK][APAD], As_i[BK][APAD], Bs_r[BK][BPAD], Bs_i[BK][BPAD];

    const int tid = threadIdx.x;
    const int tx = tid & 15, ty = tid >> 4;

    const int lrA = tid >> 2;
    const int lkA = (tid & 3) << 2;
    const int kbB = tid >> 4;            // 0..15 (B tile row = k)
    const int ncB = (tid & 15) << 2;     // 0..60

    const float* pAr0 = Ar + Aoff + (size_t)(m0+lrA)*lda + lkA;
    const float* pAi0 = Ai + Aoff + (size_t)(m0+lrA)*lda + lkA;
    const float* pAr1 = pAr0 + (size_t)64*lda;
    const float* pAi1 = pAi0 + (size_t)64*lda;
    const float* pBr  = Br + Boff + (size_t)kbB*ldb + n0 + ncB;
    const float* pBi  = Bi + Boff + (size_t)kbB*ldb + n0 + ncB;

    const unsigned baseAr = (unsigned)__cvta_generic_to_shared(&As_r[0][0]) + ty*32;
    const unsigned baseAi = (unsigned)__cvta_generic_to_shared(&As_i[0][0]) + ty*32;

    u64t cr[4][4] = {}, ci[4][4] = {};

    for (int k0 = 0; k0 < K; k0 += BK){
        const float4 a0r = *reinterpret_cast<const float4*>(pAr0 + k0);
        const float4 a0i = *reinterpret_cast<const float4*>(pAi0 + k0);
        const float4 a1r = *reinterpret_cast<const float4*>(pAr1 + k0);
        const float4 a1i = *reinterpret_cast<const float4*>(pAi1 + k0);
        const float4 b0r = *reinterpret_cast<const float4*>(pBr + (size_t)k0*ldb);
        const float4 b0i = *reinterpret_cast<const float4*>(pBi + (size_t)k0*ldb);
        As_r[lkA+0][lrA]=a0r.x; As_r[lkA+1][lrA]=a0r.y; As_r[lkA+2][lrA]=a0r.z; As_r[lkA+3][lrA]=a0r.w;
        As_i[lkA+0][lrA]=a0i.x; As_i[lkA+1][lrA]=a0i.y; As_i[lkA+2][lrA]=a0i.z; As_i[lkA+3][lrA]=a0i.w;
        As_r[lkA+0][lrA+64]=a1r.x; As_r[lkA+1][lrA+64]=a1r.y; As_r[lkA+2][lrA+64]=a1r.z; As_r[lkA+3][lrA+64]=a1r.w;
        As_i[lkA+0][lrA+64]=a1i.x; As_i[lkA+1][lrA+64]=a1i.y; As_i[lkA+2][lrA+64]=a1i.z; As_i[lkA+3][lrA+64]=a1i.w;
        *reinterpret_cast<float4*>(&Bs_r[kbB][ncB]) = b0r;
        *reinterpret_cast<float4*>(&Bs_i[kbB][ncB]) = b0i;
        __syncthreads();

        #pragma unroll
        for (int kk = 0; kk < BK; kk++){
            u64t ar[4], ai[4];
            const unsigned offk = kk*(APAD*4);
            lds2x64(ar[0], ar[1], baseAr + offk);
            lds2x64(ar[2], ar[3], baseAr + offk + 16);
            lds2x64(ai[0], ai[1], baseAi + offk);
            lds2x64(ai[2], ai[3], baseAi + offk + 16);

            const float4 b4r = *reinterpret_cast<const float4*>(&Bs_r[kk][tx<<2]);
            const float4 b4i = *reinterpret_cast<const float4*>(&Bs_i[kk][tx<<2]);
            const float brr[4] = {b4r.x,b4r.y,b4r.z,b4r.w};
            const float bii[4] = {b4i.x,b4i.y,b4i.z,b4i.w};
            u64t brd[4], bid[4], nbid[4];
            #pragma unroll
            for (int j=0;j<4;j++){
                brd[j]  = dup2(brr[j]);
                bid[j]  = dup2(bii[j]);
                nbid[j] = dup2(-bii[j]);
            }
            #pragma unroll
            for (int ip=0;ip<4;ip++){
                #pragma unroll
                for (int j=0;j<4;j++){
                    fma2(cr[ip][j], ar[ip], brd[j]);
                    fma2(cr[ip][j], ai[ip], nbid[j]);
                    fma2(ci[ip][j], ar[ip], bid[j]);
                    fma2(ci[ip][j], ai[ip], brd[j]);
                }
            }
        }
        __syncthreads();
    }

    #pragma unroll
    for (int ip=0;ip<4;ip++){
        const int gm = m0 + ty*8 + ip*2;
        #pragma unroll
        for (int j=0;j<4;j++){
            const int gn = n0 + (tx<<2) + j;
            const float2 vr = up2(cr[ip][j]);
            const float2 vi = up2(ci[ip][j]);
            const size_t i0 = Coff + (size_t)gm*ldc + gn;
            const size_t i1 = i0 + ldc;
            Cr[i0] = vr.x; Ci[i0] = vi.x;
            Cr[i1] = vr.y; Ci[i1] = vi.y;
        }
    }
}

// ---------------- launch ----------------------------------------------------
extern "C" void kernel_launch(void* const* d_in, const int* in_sizes, int n_in,
                              void* d_out, int out_size)
{
    const float* x_real   = (const float*)d_in[0];
    const float* x_imag   = (const float*)d_in[1];
    const float* ln1_g_r  = (const float*)d_in[2];
    const float* ln1_b_r  = (const float*)d_in[3];
    const float* ln1_g_i  = (const float*)d_in[4];
    const float* ln1_b_i  = (const float*)d_in[5];
    const float* ln2_g_r  = (const float*)d_in[6];
    const float* ln2_b_r  = (const float*)d_in[7];
    const float* ln2_g_i  = (const float*)d_in[8];
    const float* ln2_b_i  = (const float*)d_in[9];
    const float* qkv_w_r  = (const float*)d_in[10];
    const float* qkv_w_i  = (const float*)d_in[11];
    const float* out_w_r  = (const float*)d_in[12];
    const float* out_w_i  = (const float*)d_in[13];
    const float* out_b_r  = (const float*)d_in[14];
    const float* out_b_i  = (const float*)d_in[15];
    const float* ff_w_r   = (const float*)d_in[16];
    const float* ff_w_i   = (const float*)d_in[17];
    const float* step_sz  = (const float*)d_in[18];
    const float* lambd    = (const float*)d_in[19];

    float *xr,*xi,*xnr,*xni,*wr,*wi,*ar,*ai,*dr,*di;
    cudaGetSymbolAddress((void**)&xr,  g_x_r);
    cudaGetSymbolAddress((void**)&xi,  g_x_i);
    cudaGetSymbolAddress((void**)&xnr, g_xn_r);
    cudaGetSymbolAddress((void**)&xni, g_xn_i);
    cudaGetSymbolAddress((void**)&wr,  g_w_r);
    cudaGetSymbolAddress((void**)&wi,  g_w_i);
    cudaGetSymbolAddress((void**)&ar,  g_at_r);
    cudaGetSymbolAddress((void**)&ai,  g_at_i);
    cudaGetSymbolAddress((void**)&dr,  g_d_r);
    cudaGetSymbolAddress((void**)&di,  g_d_i);

    const int NE = ROWS*DIM;
    copy_in_kernel<<<(NE+255)/256, 256>>>(x_real, x_imag, xr, xi, NE);

    const size_t sRow = (size_t)NN*DIM;      // per-batch row-block stride
    const size_t sNN  = (size_t)NN*NN;       // per-(b,h) dots stride

    for (int l = 0; l < DEPTH; l++){
        const size_t wo = (size_t)l*DIM*DIM;
        const size_t po = (size_t)l*DIM;

        // LN1
        cln_kernel<<<ROWS,128>>>(xr,xi, ln1_g_r+po, ln1_b_r+po, ln1_g_i+po, ln1_b_i+po, xnr,xni);
        // QKV: w = xn @ Wqkv^T   (M=2048, N=512, K=512)
        cgemm_nt_kernel<0,false><<<dim3(8,16,1),256>>>(
            xnr,xni,DIM, qkv_w_r+wo,qkv_w_i+wo,DIM, wr,wi,DIM, DIM, 1.0f,
            0,0,0,0,0,0, nullptr,nullptr, nullptr,nullptr, nullptr,nullptr, 0);
        // dots[b,h] = scale * w @ conj(w)^T  (M=N=512, K=64, 32 batches)
        cgemm_nt_kernel<0,true><<<dim3(8,4,32),256>>>(
            wr,wi,DIM, wr,wi,DIM, dr,di,NN, DH, ATT_SCALE,
            sRow,(size_t)DH, sRow,(size_t)DH, (size_t)8*sNN, sNN,
            nullptr,nullptr, nullptr,nullptr, nullptr,nullptr, 0);
        // magnitude softmax, phase preserved
        csoftmax_kernel<<<BB*HEADS*NN,256>>>(dr,di);
        // att = attn @ w  (per (b,h): M=512, N=64, K=512)
        cgemm_nn_kernel<<<dim3(1,4,32),256>>>(
            dr,di,NN, wr,wi,DIM, ar,ai,DIM, NN,
            (size_t)8*sNN, sNN, sRow,(size_t)DH, sRow,(size_t)DH);
        // x = att @ Wout^T + bout + x
        cgemm_nt_kernel<1,false><<<dim3(8,16,1),256>>>(
            ar,ai,DIM, out_w_r+wo,out_w_i+wo,DIM, xr,xi,DIM, DIM, 1.0f,
            0,0,0,0,0,0, out_b_r+po,out_b_i+po, nullptr,nullptr, nullptr,nullptr, 0);
        // LN2
        cln_kernel<<<ROWS,128>>>(xr,xi, ln2_g_r+po, ln2_b_r+po, ln2_g_i+po, ln2_b_i+po, xnr,xni);
        // x = crelu(xn + ss*(xn @ Wff^T) - ss*lm)
        cgemm_nt_kernel<2,false><<<dim3(8,16,1),256>>>(
            xnr,xni,DIM, ff_w_r+wo,ff_w_i+wo,DIM, xr,xi,DIM, DIM, 1.0f,
            0,0,0,0,0,0, nullptr,nullptr, xnr,xni, step_sz,lambd, l);
    }

    copy_out_kernel<<<(NE+255)/256, 256>>>(xr, xi, (float*)d_out, NE);
}

// round 3
// speedup vs baseline: 1.1087x; 1.0442x over previous
#include <cuda_runtime.h>
#include <math.h>

#define BB 4
#define NN 512
#define DIM 512
#define HEADS 8
#define DH 64
#define DEPTH 4
#define ROWS (BB*NN)          // 2048
#define ATT_SCALE 0.125f
#define LN_EPS 1e-5f

// ---------------- scratch (static device memory; no allocation) -------------
__device__ float g_x_r [ROWS*DIM];
__device__ float g_x_i [ROWS*DIM];
__device__ float g_xn_r[ROWS*DIM];
__device__ float g_xn_i[ROWS*DIM];
__device__ float g_w_r [ROWS*DIM];
__device__ float g_w_i [ROWS*DIM];
__device__ float g_at_r[ROWS*DIM];
__device__ float g_at_i[ROWS*DIM];
__device__ float g_d_r [BB*HEADS*NN*NN];
__device__ float g_d_i [BB*HEADS*NN*NN];

// ---------------- f32x2 helpers ---------------------------------------------
typedef unsigned long long u64t;

__device__ __forceinline__ u64t dup2(float s){
    u64t r; asm("mov.b64 %0, {%1, %1};" : "=l"(r) : "f"(s)); return r;
}
__device__ __forceinline__ void fma2(u64t &d, u64t a, u64t b){
    asm("fma.rn.f32x2 %0, %1, %2, %0;" : "+l"(d) : "l"(a), "l"(b));
}
__device__ __forceinline__ void lds2x64(u64t &a, u64t &b, unsigned addr){
    asm volatile("ld.shared.v2.b64 {%0, %1}, [%2];" : "=l"(a), "=l"(b) : "r"(addr));
}
__device__ __forceinline__ float2 up2(u64t v){
    float2 f; asm("mov.b64 {%0, %1}, %2;" : "=f"(f.x), "=f"(f.y) : "l"(v)); return f;
}

__device__ __forceinline__ float warp_sum(float v){
    #pragma unroll
    for (int o=16;o;o>>=1) v += __shfl_xor_sync(0xffffffffu, v, o);
    return v;
}
__device__ __forceinline__ float warp_max(float v){
    #pragma unroll
    for (int o=16;o;o>>=1) v = fmaxf(v, __shfl_xor_sync(0xffffffffu, v, o));
    return v;
}

// ---------------- copy in / out ---------------------------------------------
__global__ void copy_in_kernel(const float* __restrict__ a, const float* __restrict__ b,
                               float* __restrict__ xr, float* __restrict__ xi, int n){
    int i = blockIdx.x*blockDim.x + threadIdx.x;
    if (i < n){ xr[i] = a[i]; xi[i] = b[i]; }
}
__global__ void copy_out_kernel(const float* __restrict__ xr, const float* __restrict__ xi,
                                float* __restrict__ out, int n){
    int i = blockIdx.x*blockDim.x + threadIdx.x;
    if (i < n){ out[i] = xr[i]; out[n+i] = xi[i]; }
}

// ---------------- complex LayerNorm (per row of 512) ------------------------
__global__ __launch_bounds__(128)
void cln_kernel(const float* __restrict__ xr, const float* __restrict__ xi,
                const float* __restrict__ gr, const float* __restrict__ br,
                const float* __restrict__ gi, const float* __restrict__ bi,
                float* __restrict__ outr, float* __restrict__ outi)
{
    const int row = blockIdx.x;
    const int t   = threadIdx.x;
    const float4 vr = reinterpret_cast<const float4*>(xr + (size_t)row*DIM)[t];
    const float4 vi = reinterpret_cast<const float4*>(xi + (size_t)row*DIM)[t];

    float sr  = vr.x+vr.y+vr.z+vr.w;
    float s2r = vr.x*vr.x+vr.y*vr.y+vr.z*vr.z+vr.w*vr.w;
    float si  = vi.x+vi.y+vi.z+vi.w;
    float s2i = vi.x*vi.x+vi.y*vi.y+vi.z*vi.z+vi.w*vi.w;

    sr = warp_sum(sr); s2r = warp_sum(s2r); si = warp_sum(si); s2i = warp_sum(s2i);

    __shared__ float red[4][4];
    const int wid = t >> 5, lane = t & 31;
    if (lane == 0){ red[wid][0]=sr; red[wid][1]=s2r; red[wid][2]=si; red[wid][3]=s2i; }
    __syncthreads();
    float tr=0,t2r=0,ti=0,t2i=0;
    #pragma unroll
    for (int w=0; w<4; w++){ tr+=red[w][0]; t2r+=red[w][1]; ti+=red[w][2]; t2i+=red[w][3]; }

    const float inv = 1.0f/DIM;
    const float mr = tr*inv,  vvr = t2r*inv - mr*mr;
    const float mi = ti*inv,  vvi = t2i*inv - mi*mi;
    const float rr = rsqrtf(vvr + LN_EPS);
    const float ri = rsqrtf(vvi + LN_EPS);

    const float4 g4r = reinterpret_cast<const float4*>(gr)[t];
    const float4 b4r = reinterpret_cast<const float4*>(br)[t];
    const float4 g4i = reinterpret_cast<const float4*>(gi)[t];
    const float4 b4i = reinterpret_cast<const float4*>(bi)[t];

    float4 orr, oii;
    orr.x = (vr.x-mr)*rr*g4r.x + b4r.x;  oii.x = (vi.x-mi)*ri*g4i.x + b4i.x;
    orr.y = (vr.y-mr)*rr*g4r.y + b4r.y;  oii.y = (vi.y-mi)*ri*g4i.y + b4i.y;
    orr.z = (vr.z-mr)*rr*g4r.z + b4r.z;  oii.z = (vi.z-mi)*ri*g4i.z + b4i.z;
    orr.w = (vr.w-mr)*rr*g4r.w + b4r.w;  oii.w = (vi.w-mi)*ri*g4i.w + b4i.w;
    reinterpret_cast<float4*>(outr + (size_t)row*DIM)[t] = orr;
    reinterpret_cast<float4*>(outi + (size_t)row*DIM)[t] = oii;
}

// ---------------- magnitude softmax: one warp per row, no barriers ----------
__global__ __launch_bounds__(256)
void csoftmax_kernel(float* __restrict__ zr, float* __restrict__ zi)
{
    const int wid = threadIdx.x >> 5, lane = threadIdx.x & 31;
    const size_t row = (size_t)blockIdx.x*8 + wid;
    float* pr = zr + row*NN;
    float* pi = zi + row*NN;

    float4 vr[4], vi[4];
    #pragma unroll
    for (int u=0;u<4;u++){
        vr[u] = reinterpret_cast<const float4*>(pr)[lane + 32*u];
        vi[u] = reinterpret_cast<const float4*>(pi)[lane + 32*u];
    }
    float m[16];
    #pragma unroll
    for (int u=0;u<4;u++){
        m[4*u+0] = sqrtf(vr[u].x*vr[u].x + vi[u].x*vi[u].x);
        m[4*u+1] = sqrtf(vr[u].y*vr[u].y + vi[u].y*vi[u].y);
        m[4*u+2] = sqrtf(vr[u].z*vr[u].z + vi[u].z*vi[u].z);
        m[4*u+3] = sqrtf(vr[u].w*vr[u].w + vi[u].w*vi[u].w);
    }
    float mx = m[0];
    #pragma unroll
    for (int e=1;e<16;e++) mx = fmaxf(mx, m[e]);
    mx = warp_max(mx);

    float ex[16]; float s = 0.f;
    #pragma unroll
    for (int e=0;e<16;e++){ ex[e] = __expf(m[e] - mx); s += ex[e]; }
    s = warp_sum(s);
    const float inv = 1.0f / s;

    #pragma unroll
    for (int u=0;u<4;u++){
        float sc;
        sc = (m[4*u+0] > 0.f) ? ex[4*u+0]*inv/m[4*u+0] : 0.f;
        if (m[4*u+0] > 0.f){ vr[u].x *= sc; vi[u].x *= sc; } else { vr[u].x = ex[4*u+0]*inv; vi[u].x = 0.f; }
        sc = (m[4*u+1] > 0.f) ? ex[4*u+1]*inv/m[4*u+1] : 0.f;
        if (m[4*u+1] > 0.f){ vr[u].y *= sc; vi[u].y *= sc; } else { vr[u].y = ex[4*u+1]*inv; vi[u].y = 0.f; }
        sc = (m[4*u+2] > 0.f) ? ex[4*u+2]*inv/m[4*u+2] : 0.f;
        if (m[4*u+2] > 0.f){ vr[u].z *= sc; vi[u].z *= sc; } else { vr[u].z = ex[4*u+2]*inv; vi[u].z = 0.f; }
        sc = (m[4*u+3] > 0.f) ? ex[4*u+3]*inv/m[4*u+3] : 0.f;
        if (m[4*u+3] > 0.f){ vr[u].w *= sc; vi[u].w *= sc; } else { vr[u].w = ex[4*u+3]*inv; vi[u].w = 0.f; }
        reinterpret_cast<float4*>(pr)[lane + 32*u] = vr[u];
        reinterpret_cast<float4*>(pi)[lane + 32*u] = vi[u];
    }
}

// ======================= f32x2 complex GEMM (pipelined) ======================
#define BM 128
#define BN 64
#define BK 16
#define APAD 132
#define BPAD 68

// ---- NT: C[m,n] = alpha * sum_k A[m,k] * (conj?) B[n,k] --------------------
template<int EPI, bool CONJB>
__global__ __launch_bounds__(256, 2)
void cgemm_nt_kernel(const float* __restrict__ Ar, const float* __restrict__ Ai, int lda,
                     const float* __restrict__ Br, const float* __restrict__ Bi, int ldb,
                     float* Cr, float* Ci, int ldc,
                     int K, float alpha,
                     size_t sAb, size_t sAh, size_t sBb, size_t sBh,
                     size_t sCb, size_t sCh,
                     const float* __restrict__ biasR, const float* __restrict__ biasI,
                     const float* __restrict__ Xr, const float* __restrict__ Xi,
                     const float* __restrict__ ssp, const float* __restrict__ lmp, int layer)
{
    const int zb = blockIdx.z >> 3, zh = blockIdx.z & 7;
    const size_t Aoff = (size_t)zb*sAb + (size_t)zh*sAh;
    const size_t Boff = (size_t)zb*sBb + (size_t)zh*sBh;
    const size_t Coff = (size_t)zb*sCb + (size_t)zh*sCh;

    const int m0 = blockIdx.y * BM;
    const int n0 = blockIdx.x * BN;

    __shared__ float As_r[BK][APAD], As_i[BK][APAD], Bs_r[BK][BPAD], Bs_i[BK][BPAD];

    const int tid = threadIdx.x;
    const int tx = tid & 15, ty = tid >> 4;

    const int lrA = tid >> 2;            // 0..63 (rows lrA and lrA+64)
    const int lkA = (tid & 3) << 2;      // 0,4,8,12
    const int nB  = tid >> 2;
    const int lkB = (tid & 3) << 2;

    const float* pAr0 = Ar + Aoff + (size_t)(m0+lrA)*lda + lkA;
    const float* pAi0 = Ai + Aoff + (size_t)(m0+lrA)*lda + lkA;
    const float* pAr1 = pAr0 + (size_t)64*lda;
    const float* pAi1 = pAi0 + (size_t)64*lda;
    const float* pBr  = Br + Boff + (size_t)(n0+nB)*ldb + lkB;
    const float* pBi  = Bi + Boff + (size_t)(n0+nB)*ldb + lkB;

    const unsigned baseAr = (unsigned)__cvta_generic_to_shared(&As_r[0][0]) + ty*32;
    const unsigned baseAi = (unsigned)__cvta_generic_to_shared(&As_i[0][0]) + ty*32;

    u64t cr[4][4] = {}, ci[4][4] = {};

    // prologue prefetch (iter 0)
    float4 fa0r = *reinterpret_cast<const float4*>(pAr0);
    float4 fa0i = *reinterpret_cast<const float4*>(pAi0);
    float4 fa1r = *reinterpret_cast<const float4*>(pAr1);
    float4 fa1i = *reinterpret_cast<const float4*>(pAi1);
    float4 fbr  = *reinterpret_cast<const float4*>(pBr);
    float4 fbi  = *reinterpret_cast<const float4*>(pBi);

    for (int k0 = 0; k0 < K; k0 += BK){
        // commit staged regs to smem
        As_r[lkA+0][lrA]=fa0r.x; As_r[lkA+1][lrA]=fa0r.y; As_r[lkA+2][lrA]=fa0r.z; As_r[lkA+3][lrA]=fa0r.w;
        As_i[lkA+0][lrA]=fa0i.x; As_i[lkA+1][lrA]=fa0i.y; As_i[lkA+2][lrA]=fa0i.z; As_i[lkA+3][lrA]=fa0i.w;
        As_r[lkA+0][lrA+64]=fa1r.x; As_r[lkA+1][lrA+64]=fa1r.y; As_r[lkA+2][lrA+64]=fa1r.z; As_r[lkA+3][lrA+64]=fa1r.w;
        As_i[lkA+0][lrA+64]=fa1i.x; As_i[lkA+1][lrA+64]=fa1i.y; As_i[lkA+2][lrA+64]=fa1i.z; As_i[lkA+3][lrA+64]=fa1i.w;
        Bs_r[lkB+0][nB]=fbr.x; Bs_r[lkB+1][nB]=fbr.y; Bs_r[lkB+2][nB]=fbr.z; Bs_r[lkB+3][nB]=fbr.w;
        Bs_i[lkB+0][nB]=fbi.x; Bs_i[lkB+1][nB]=fbi.y; Bs_i[lkB+2][nB]=fbi.z; Bs_i[lkB+3][nB]=fbi.w;
        __syncthreads();

        // issue next iteration's global loads early (latency hidden by compute)
        const int kn = k0 + BK;
        if (kn < K){
            fa0r = *reinterpret_cast<const float4*>(pAr0 + kn);
            fa0i = *reinterpret_cast<const float4*>(pAi0 + kn);
            fa1r = *reinterpret_cast<const float4*>(pAr1 + kn);
            fa1i = *reinterpret_cast<const float4*>(pAi1 + kn);
            fbr  = *reinterpret_cast<const float4*>(pBr  + kn);
            fbi  = *reinterpret_cast<const float4*>(pBi  + kn);
        }

        #pragma unroll
        for (int kk = 0; kk < BK; kk++){
            u64t ar[4], ai[4];
            const unsigned offk = kk*(APAD*4);
            lds2x64(ar[0], ar[1], baseAr + offk);
            lds2x64(ar[2], ar[3], baseAr + offk + 16);
            lds2x64(ai[0], ai[1], baseAi + offk);
            lds2x64(ai[2], ai[3], baseAi + offk + 16);

            const float4 b4r = *reinterpret_cast<const float4*>(&Bs_r[kk][tx<<2]);
            const float4 b4i = *reinterpret_cast<const float4*>(&Bs_i[kk][tx<<2]);
            const float brr[4] = {b4r.x,b4r.y,b4r.z,b4r.w};
            const float bii[4] = {b4i.x,b4i.y,b4i.z,b4i.w};
            #pragma unroll
            for (int j=0;j<4;j++){
                const u64t brd  = dup2(brr[j]);
                const u64t bid  = dup2(bii[j]);
                const u64t nbid = dup2(-bii[j]);
                #pragma unroll
                for (int ip=0;ip<4;ip++){
                    if (CONJB){
                        fma2(cr[ip][j], ar[ip], brd);
                        fma2(cr[ip][j], ai[ip], bid);
                        fma2(ci[ip][j], ai[ip], brd);
                        fma2(ci[ip][j], ar[ip], nbid);
                    } else {
                        fma2(cr[ip][j], ar[ip], brd);
                        fma2(cr[ip][j], ai[ip], nbid);
                        fma2(ci[ip][j], ar[ip], bid);
                        fma2(ci[ip][j], ai[ip], brd);
                    }
                }
            }
        }
        __syncthreads();
    }

    float ss = 0.f, lm = 0.f;
    if (EPI == 2){
        ss = log1pf(expf(ssp[layer]));
        lm = log1pf(expf(lmp[layer]));
    }

    #pragma unroll
    for (int ip=0;ip<4;ip++){
        const int gm = m0 + ty*8 + ip*2;
        #pragma unroll
        for (int j=0;j<4;j++){
            const int gn = n0 + (tx<<2) + j;
            float2 vr = up2(cr[ip][j]);
            float2 vi = up2(ci[ip][j]);
            vr.x *= alpha; vr.y *= alpha; vi.x *= alpha; vi.y *= alpha;
            const size_t i0 = Coff + (size_t)gm*ldc + gn;
            const size_t i1 = i0 + ldc;
            if (EPI == 0){
                Cr[i0] = vr.x; Ci[i0] = vi.x;
                Cr[i1] = vr.y; Ci[i1] = vi.y;
            } else if (EPI == 1){
                Cr[i0] = vr.x + biasR[gn] + Cr[i0];
                Ci[i0] = vi.x + biasI[gn] + Ci[i0];
                Cr[i1] = vr.y + biasR[gn] + Cr[i1];
                Ci[i1] = vi.y + biasI[gn] + Ci[i1];
            } else {
                const float x0r = Xr[(size_t)gm*ldc + gn];
                const float x0i = Xi[(size_t)gm*ldc + gn];
                const float x1r = Xr[(size_t)(gm+1)*ldc + gn];
                const float x1i = Xi[(size_t)(gm+1)*ldc + gn];
                Cr[i0] = fmaxf(fmaf(ss, vr.x, x0r) - ss*lm, 0.f);
                Ci[i0] = fmaxf(fmaf(ss, vi.x, x0i), 0.f);
                Cr[i1] = fmaxf(fmaf(ss, vr.y, x1r) - ss*lm, 0.f);
                Ci[i1] = fmaxf(fmaf(ss, vi.y, x1i), 0.f);
            }
        }
    }
}

// ---- NN: C[m,n] = sum_k A[m,k] * B[k,n] ------------------------------------
__global__ __launch_bounds__(256, 2)
void cgemm_nn_kernel(const float* __restrict__ Ar, const float* __restrict__ Ai, int lda,
                     const float* __restrict__ Br, const float* __restrict__ Bi, int ldb,
                     float* __restrict__ Cr, float* __restrict__ Ci, int ldc,
                     int K,
                     size_t sAb, size_t sAh, size_t sBb, size_t sBh,
                     size_t sCb, size_t sCh)
{
    const int zb = blockIdx.z >> 3, zh = blockIdx.z & 7;
    const size_t Aoff = (size_t)zb*sAb + (size_t)zh*sAh;
    const size_t Boff = (size_t)zb*sBb + (size_t)zh*sBh;
    const size_t Coff = (size_t)zb*sCb + (size_t)zh*sCh;

    const int m0 = blockIdx.y * BM;
    const int n0 = blockIdx.x * BN;

    __shared__ float As_r[BK][APAD], As_i[BK][APAD], Bs_r[BK][BPAD], Bs_i[BK][BPAD];

    const int tid = threadIdx.x;
    const int tx = tid & 15, ty = tid >> 4;

    const int lrA = tid >> 2;
    const int lkA = (tid & 3) << 2;
    const int kbB = tid >> 4;            // 0..15 (B tile row = k)
    const int ncB = (tid & 15) << 2;     // 0..60

    const float* pAr0 = Ar + Aoff + (size_t)(m0+lrA)*lda + lkA;
    const float* pAi0 = Ai + Aoff + (size_t)(m0+lrA)*lda + lkA;
    const float* pAr1 = pAr0 + (size_t)64*lda;
    const float* pAi1 = pAi0 + (size_t)64*lda;
    const float* pBr  = Br + Boff + (size_t)kbB*ldb + n0 + ncB;
    const float* pBi  = Bi + Boff + (size_t)kbB*ldb + n0 + ncB;

    const unsigned baseAr = (unsigned)__cvta_generic_to_shared(&As_r[0][0]) + ty*32;
    const unsigned baseAi = (unsigned)__cvta_generic_to_shared(&As_i[0][0]) + ty*32;

    u64t cr[4][4] = {}, ci[4][4] = {};

    float4 fa0r = *reinterpret_cast<const float4*>(pAr0);
    float4 fa0i = *reinterpret_cast<const float4*>(pAi0);
    float4 fa1r = *reinterpret_cast<const float4*>(pAr1);
    float4 fa1i = *reinterpret_cast<const float4*>(pAi1);
    float4 fbr  = *reinterpret_cast<const float4*>(pBr);
    float4 fbi  = *reinterpret_cast<const float4*>(pBi);

    for (int k0 = 0; k0 < K; k0 += BK){
        As_r[lkA+0][lrA]=fa0r.x; As_r[lkA+1][lrA]=fa0r.y; As_r[lkA+2][lrA]=fa0r.z; As_r[lkA+3][lrA]=fa0r.w;
        As_i[lkA+0][lrA]=fa0i.x; As_i[lkA+1][lrA]=fa0i.y; As_i[lkA+2][lrA]=fa0i.z; As_i[lkA+3][lrA]=fa0i.w;
        As_r[lkA+0][lrA+64]=fa1r.x; As_r[lkA+1][lrA+64]=fa1r.y; As_r[lkA+2][lrA+64]=fa1r.z; As_r[lkA+3][lrA+64]=fa1r.w;
        As_i[lkA+0][lrA+64]=fa1i.x; As_i[lkA+1][lrA+64]=fa1i.y; As_i[lkA+2][lrA+64]=fa1i.z; As_i[lkA+3][lrA+64]=fa1i.w;
        *reinterpret_cast<float4*>(&Bs_r[kbB][ncB]) = fbr;
        *reinterpret_cast<float4*>(&Bs_i[kbB][ncB]) = fbi;
        __syncthreads();

        const int kn = k0 + BK;
        if (kn < K){
            fa0r = *reinterpret_cast<const float4*>(pAr0 + kn);
            fa0i = *reinterpret_cast<const float4*>(pAi0 + kn);
            fa1r = *reinterpret_cast<const float4*>(pAr1 + kn);
            fa1i = *reinterpret_cast<const float4*>(pAi1 + kn);
            fbr  = *reinterpret_cast<const float4*>(pBr + (size_t)kn*ldb);
            fbi  = *reinterpret_cast<const float4*>(pBi + (size_t)kn*ldb);
        }

        #pragma unroll
        for (int kk = 0; kk < BK; kk++){
            u64t ar[4], ai[4];
            const unsigned offk = kk*(APAD*4);
            lds2x64(ar[0], ar[1], baseAr + offk);
            lds2x64(ar[2], ar[3], baseAr + offk + 16);
            lds2x64(ai[0], ai[1], baseAi + offk);
            lds2x64(ai[2], ai[3], baseAi + offk + 16);

            const float4 b4r = *reinterpret_cast<const float4*>(&Bs_r[kk][tx<<2]);
            const float4 b4i = *reinterpret_cast<const float4*>(&Bs_i[kk][tx<<2]);
            const float brr[4] = {b4r.x,b4r.y,b4r.z,b4r.w};
            const float bii[4] = {b4i.x,b4i.y,b4i.z,b4i.w};
            #pragma unroll
            for (int j=0;j<4;j++){
                const u64t brd  = dup2(brr[j]);
                const u64t bid  = dup2(bii[j]);
                const u64t nbid = dup2(-bii[j]);
                #pragma unroll
                for (int ip=0;ip<4;ip++){
                    fma2(cr[ip][j], ar[ip], brd);
                    fma2(cr[ip][j], ai[ip], nbid);
                    fma2(ci[ip][j], ar[ip], bid);
                    fma2(ci[ip][j], ai[ip], brd);
                }
            }
        }
        __syncthreads();
    }

    #pragma unroll
    for (int ip=0;ip<4;ip++){
        const int gm = m0 + ty*8 + ip*2;
        #pragma unroll
        for (int j=0;j<4;j++){
            const int gn = n0 + (tx<<2) + j;
            const float2 vr = up2(cr[ip][j]);
            const float2 vi = up2(ci[ip][j]);
            const size_t i0 = Coff + (size_t)gm*ldc + gn;
            const size_t i1 = i0 + ldc;
            Cr[i0] = vr.x; Ci[i0] = vi.x;
            Cr[i1] = vr.y; Ci[i1] = vi.y;
        }
    }
}

// ---------------- launch ----------------------------------------------------
extern "C" void kernel_launch(void* const* d_in, const int* in_sizes, int n_in,
                              void* d_out, int out_size)
{
    const float* x_real   = (const float*)d_in[0];
    const float* x_imag   = (const float*)d_in[1];
    const float* ln1_g_r  = (const float*)d_in[2];
    const float* ln1_b_r  = (const float*)d_in[3];
    const float* ln1_g_i  = (const float*)d_in[4];
    const float* ln1_b_i  = (const float*)d_in[5];
    const float* ln2_g_r  = (const float*)d_in[6];
    const float* ln2_b_r  = (const float*)d_in[7];
    const float* ln2_g_i  = (const float*)d_in[8];
    const float* ln2_b_i  = (const float*)d_in[9];
    const float* qkv_w_r  = (const float*)d_in[10];
    const float* qkv_w_i  = (const float*)d_in[11];
    const float* out_w_r  = (const float*)d_in[12];
    const float* out_w_i  = (const float*)d_in[13];
    const float* out_b_r  = (const float*)d_in[14];
    const float* out_b_i  = (const float*)d_in[15];
    const float* ff_w_r   = (const float*)d_in[16];
    const float* ff_w_i   = (const float*)d_in[17];
    const float* step_sz  = (const float*)d_in[18];
    const float* lambd    = (const float*)d_in[19];

    float *xr,*xi,*xnr,*xni,*wr,*wi,*ar,*ai,*dr,*di;
    cudaGetSymbolAddress((void**)&xr,  g_x_r);
    cudaGetSymbolAddress((void**)&xi,  g_x_i);
    cudaGetSymbolAddress((void**)&xnr, g_xn_r);
    cudaGetSymbolAddress((void**)&xni, g_xn_i);
    cudaGetSymbolAddress((void**)&wr,  g_w_r);
    cudaGetSymbolAddress((void**)&wi,  g_w_i);
    cudaGetSymbolAddress((void**)&ar,  g_at_r);
    cudaGetSymbolAddress((void**)&ai,  g_at_i);
    cudaGetSymbolAddress((void**)&dr,  g_d_r);
    cudaGetSymbolAddress((void**)&di,  g_d_i);

    const int NE = ROWS*DIM;
    copy_in_kernel<<<(NE+255)/256, 256>>>(x_real, x_imag, xr, xi, NE);

    const size_t sRow = (size_t)NN*DIM;
    const size_t sNN  = (size_t)NN*NN;

    for (int l = 0; l < DEPTH; l++){
        const size_t wo = (size_t)l*DIM*DIM;
        const size_t po = (size_t)l*DIM;

        // LN1
        cln_kernel<<<ROWS,128>>>(xr,xi, ln1_g_r+po, ln1_b_r+po, ln1_g_i+po, ln1_b_i+po, xnr,xni);
        // QKV: w = xn @ Wqkv^T
        cgemm_nt_kernel<0,false><<<dim3(8,16,1),256>>>(
            xnr,xni,DIM, qkv_w_r+wo,qkv_w_i+wo,DIM, wr,wi,DIM, DIM, 1.0f,
            0,0,0,0,0,0, nullptr,nullptr, nullptr,nullptr, nullptr,nullptr, 0);
        // dots[b,h] = scale * w @ conj(w)^T  (K=64)
        cgemm_nt_kernel<0,true><<<dim3(8,4,32),256>>>(
            wr,wi,DIM, wr,wi,DIM, dr,di,NN, DH, ATT_SCALE,
            sRow,(size_t)DH, sRow,(size_t)DH, (size_t)8*sNN, sNN,
            nullptr,nullptr, nullptr,nullptr, nullptr,nullptr, 0);
        // magnitude softmax (warp per row)
        csoftmax_kernel<<<BB*HEADS*NN/8,256>>>(dr,di);
        // att = attn @ w
        cgemm_nn_kernel<<<dim3(1,4,32),256>>>(
            dr,di,NN, wr,wi,DIM, ar,ai,DIM, NN,
            (size_t)8*sNN, sNN, sRow,(size_t)DH, sRow,(size_t)DH);
        // x = att @ Wout^T + bout + x
        cgemm_nt_kernel<1,false><<<dim3(8,16,1),256>>>(
            ar,ai,DIM, out_w_r+wo,out_w_i+wo,DIM, xr,xi,DIM, DIM, 1.0f,
            0,0,0,0,0,0, out_b_r+po,out_b_i+po, nullptr,nullptr, nullptr,nullptr, 0);
        // LN2
        cln_kernel<<<ROWS,128>>>(xr,xi, ln2_g_r+po, ln2_b_r+po, ln2_g_i+po, ln2_b_i+po, xnr,xni);
        // x = crelu(xn + ss*(xn @ Wff^T) - ss*lm)
        cgemm_nt_kernel<2,false><<<dim3(8,16,1),256>>>(
            xnr,xni,DIM, ff_w_r+wo,ff_w_i+wo,DIM, xr,xi,DIM, DIM, 1.0f,
            0,0,0,0,0,0, nullptr,nullptr, xnr,xni, step_sz,lambd, l);
    }

    copy_out_kernel<<<(NE+255)/256, 256>>>(xr, xi, (float*)d_out, NE);
}

// round 4
// speedup vs baseline: 1.1484x; 1.0358x over previous
#include <cuda_runtime.h>
#include <math.h>

#define BB 4
#define NN 512
#define DIM 512
#define HEADS 8
#define DH 64
#define DEPTH 4
#define ROWS (BB*NN)          // 2048
#define ATT_SCALE 0.125f
#define LN_EPS 1e-5f

// ---------------- scratch (static device memory; no allocation) -------------
__device__ float g_x_r [ROWS*DIM];
__device__ float g_x_i [ROWS*DIM];
__device__ float g_xn_r[ROWS*DIM];
__device__ float g_xn_i[ROWS*DIM];
__device__ float g_w_r [ROWS*DIM];
__device__ float g_w_i [ROWS*DIM];
__device__ float g_at_r[ROWS*DIM];
__device__ float g_at_i[ROWS*DIM];
__device__ float g_d_r [BB*HEADS*NN*NN];
__device__ float g_d_i [BB*HEADS*NN*NN];

// ---------------- f32x2 / async helpers -------------------------------------
typedef unsigned long long u64t;

__device__ __forceinline__ u64t dup2(float s){
    u64t r; asm("mov.b64 %0, {%1, %1};" : "=l"(r) : "f"(s)); return r;
}
__device__ __forceinline__ void fma2(u64t &d, u64t a, u64t b){
    asm("fma.rn.f32x2 %0, %1, %2, %0;" : "+l"(d) : "l"(a), "l"(b));
}
__device__ __forceinline__ void lds2x64(u64t &a, u64t &b, unsigned addr){
    asm volatile("ld.shared.v2.b64 {%0, %1}, [%2];" : "=l"(a), "=l"(b) : "r"(addr));
}
__device__ __forceinline__ float2 up2(u64t v){
    float2 f; asm("mov.b64 {%0, %1}, %2;" : "=f"(f.x), "=f"(f.y) : "l"(v)); return f;
}
__device__ __forceinline__ void cpa4(unsigned dst, const float* src){
    asm volatile("cp.async.ca.shared.global [%0], [%1], 4;" :: "r"(dst), "l"(src));
}
__device__ __forceinline__ void cpa16(unsigned dst, const float* src){
    asm volatile("cp.async.cg.shared.global [%0], [%1], 16;" :: "r"(dst), "l"(src));
}
#define CP_COMMIT() asm volatile("cp.async.commit_group;")
#define CP_WAIT1()  asm volatile("cp.async.wait_group 1;")

__device__ __forceinline__ float warp_sum(float v){
    #pragma unroll
    for (int o=16;o;o>>=1) v += __shfl_xor_sync(0xffffffffu, v, o);
    return v;
}
__device__ __forceinline__ float warp_max(float v){
    #pragma unroll
    for (int o=16;o;o>>=1) v = fmaxf(v, __shfl_xor_sync(0xffffffffu, v, o));
    return v;
}

// ---------------- copy in / out ---------------------------------------------
__global__ void copy_in_kernel(const float* __restrict__ a, const float* __restrict__ b,
                               float* __restrict__ xr, float* __restrict__ xi, int n){
    int i = blockIdx.x*blockDim.x + threadIdx.x;
    if (i < n){ xr[i] = a[i]; xi[i] = b[i]; }
}
__global__ void copy_out_kernel(const float* __restrict__ xr, const float* __restrict__ xi,
                                float* __restrict__ out, int n){
    int i = blockIdx.x*blockDim.x + threadIdx.x;
    if (i < n){ out[i] = xr[i]; out[n+i] = xi[i]; }
}

// ---------------- complex LayerNorm (per row of 512) ------------------------
__global__ __launch_bounds__(128)
void cln_kernel(const float* __restrict__ xr, const float* __restrict__ xi,
                const float* __restrict__ gr, const float* __restrict__ br,
                const float* __restrict__ gi, const float* __restrict__ bi,
                float* __restrict__ outr, float* __restrict__ outi)
{
    const int row = blockIdx.x;
    const int t   = threadIdx.x;
    const float4 vr = reinterpret_cast<const float4*>(xr + (size_t)row*DIM)[t];
    const float4 vi = reinterpret_cast<const float4*>(xi + (size_t)row*DIM)[t];

    float sr  = vr.x+vr.y+vr.z+vr.w;
    float s2r = vr.x*vr.x+vr.y*vr.y+vr.z*vr.z+vr.w*vr.w;
    float si  = vi.x+vi.y+vi.z+vi.w;
    float s2i = vi.x*vi.x+vi.y*vi.y+vi.z*vi.z+vi.w*vi.w;

    sr = warp_sum(sr); s2r = warp_sum(s2r); si = warp_sum(si); s2i = warp_sum(s2i);

    __shared__ float red[4][4];
    const int wid = t >> 5, lane = t & 31;
    if (lane == 0){ red[wid][0]=sr; red[wid][1]=s2r; red[wid][2]=si; red[wid][3]=s2i; }
    __syncthreads();
    float tr=0,t2r=0,ti=0,t2i=0;
    #pragma unroll
    for (int w=0; w<4; w++){ tr+=red[w][0]; t2r+=red[w][1]; ti+=red[w][2]; t2i+=red[w][3]; }

    const float inv = 1.0f/DIM;
    const float mr = tr*inv,  vvr = t2r*inv - mr*mr;
    const float mi = ti*inv,  vvi = t2i*inv - mi*mi;
    const float rr = rsqrtf(vvr + LN_EPS);
    const float ri = rsqrtf(vvi + LN_EPS);

    const float4 g4r = reinterpret_cast<const float4*>(gr)[t];
    const float4 b4r = reinterpret_cast<const float4*>(br)[t];
    const float4 g4i = reinterpret_cast<const float4*>(gi)[t];
    const float4 b4i = reinterpret_cast<const float4*>(bi)[t];

    float4 orr, oii;
    orr.x = (vr.x-mr)*rr*g4r.x + b4r.x;  oii.x = (vi.x-mi)*ri*g4i.x + b4i.x;
    orr.y = (vr.y-mr)*rr*g4r.y + b4r.y;  oii.y = (vi.y-mi)*ri*g4i.y + b4i.y;
    orr.z = (vr.z-mr)*rr*g4r.z + b4r.z;  oii.z = (vi.z-mi)*ri*g4i.z + b4i.z;
    orr.w = (vr.w-mr)*rr*g4r.w + b4r.w;  oii.w = (vi.w-mi)*ri*g4i.w + b4i.w;
    reinterpret_cast<float4*>(outr + (size_t)row*DIM)[t] = orr;
    reinterpret_cast<float4*>(outi + (size_t)row*DIM)[t] = oii;
}

// ---------------- magnitude softmax: one warp per row, no barriers ----------
__global__ __launch_bounds__(256)
void csoftmax_kernel(float* __restrict__ zr, float* __restrict__ zi)
{
    const int wid = threadIdx.x >> 5, lane = threadIdx.x & 31;
    const size_t row = (size_t)blockIdx.x*8 + wid;
    float* pr = zr + row*NN;
    float* pi = zi + row*NN;

    float4 vr[4], vi[4];
    #pragma unroll
    for (int u=0;u<4;u++){
        vr[u] = reinterpret_cast<const float4*>(pr)[lane + 32*u];
        vi[u] = reinterpret_cast<const float4*>(pi)[lane + 32*u];
    }
    float m[16];
    #pragma unroll
    for (int u=0;u<4;u++){
        m[4*u+0] = sqrtf(vr[u].x*vr[u].x + vi[u].x*vi[u].x);
        m[4*u+1] = sqrtf(vr[u].y*vr[u].y + vi[u].y*vi[u].y);
        m[4*u+2] = sqrtf(vr[u].z*vr[u].z + vi[u].z*vi[u].z);
        m[4*u+3] = sqrtf(vr[u].w*vr[u].w + vi[u].w*vi[u].w);
    }
    float mx = m[0];
    #pragma unroll
    for (int e=1;e<16;e++) mx = fmaxf(mx, m[e]);
    mx = warp_max(mx);

    float ex[16]; float s = 0.f;
    #pragma unroll
    for (int e=0;e<16;e++){ ex[e] = __expf(m[e] - mx); s += ex[e]; }
    s = warp_sum(s);
    const float inv = 1.0f / s;

    #pragma unroll
    for (int u=0;u<4;u++){
        float sc;
        sc = (m[4*u+0] > 0.f) ? ex[4*u+0]*inv/m[4*u+0] : 0.f;
        if (m[4*u+0] > 0.f){ vr[u].x *= sc; vi[u].x *= sc; } else { vr[u].x = ex[4*u+0]*inv; vi[u].x = 0.f; }
        sc = (m[4*u+1] > 0.f) ? ex[4*u+1]*inv/m[4*u+1] : 0.f;
        if (m[4*u+1] > 0.f){ vr[u].y *= sc; vi[u].y *= sc; } else { vr[u].y = ex[4*u+1]*inv; vi[u].y = 0.f; }
        sc = (m[4*u+2] > 0.f) ? ex[4*u+2]*inv/m[4*u+2] : 0.f;
        if (m[4*u+2] > 0.f){ vr[u].z *= sc; vi[u].z *= sc; } else { vr[u].z = ex[4*u+2]*inv; vi[u].z = 0.f; }
        sc = (m[4*u+3] > 0.f) ? ex[4*u+3]*inv/m[4*u+3] : 0.f;
        if (m[4*u+3] > 0.f){ vr[u].w *= sc; vi[u].w *= sc; } else { vr[u].w = ex[4*u+3]*inv; vi[u].w = 0.f; }
        reinterpret_cast<float4*>(pr)[lane + 32*u] = vr[u];
        reinterpret_cast<float4*>(pi)[lane + 32*u] = vi[u];
    }
}

// ======================= f32x2 complex GEMM (cp.async, 3-stage) ==============
#define BM 128
#define BN 64
#define BK 16
#define APAD 132           // row stride floats (528B, 16B aligned)
#define BPAD 68            // 272B, 16B aligned
#define A_STAGE_F (BK*APAD)      // 2112 floats
#define B_STAGE_F (BK*BPAD)      // 1088 floats
#define A_STAGE_B (A_STAGE_F*4)  // 8448 bytes
#define B_STAGE_B (B_STAGE_F*4)  // 4352 bytes
#define SMEM_BYTES (3*(2*A_STAGE_B + 2*B_STAGE_B))   // 76800

// ---- NT: C[m,n] = alpha * sum_k A[m,k] * (conj?) B[n,k] --------------------
template<int EPI, bool CONJB>
__global__ __launch_bounds__(256, 2)
void cgemm_nt_kernel(const float* __restrict__ Ar, const float* __restrict__ Ai, int lda,
                     const float* __restrict__ Br, const float* __restrict__ Bi, int ldb,
                     float* Cr, float* Ci, int ldc,
                     int K, float alpha,
                     size_t sAb, size_t sAh, size_t sBb, size_t sBh,
                     size_t sCb, size_t sCh,
                     const float* __restrict__ biasR, const float* __restrict__ biasI,
                     const float* __restrict__ Xr, const float* __restrict__ Xi,
                     const float* __restrict__ ssp, const float* __restrict__ lmp, int layer)
{
    extern __shared__ float dsm[];
    float* AsR = dsm;
    float* AsI = AsR + 3*A_STAGE_F;
    float* BsR = AsI + 3*A_STAGE_F;
    float* BsI = BsR + 3*B_STAGE_F;
    const unsigned aR = (unsigned)__cvta_generic_to_shared(AsR);
    const unsigned aI = (unsigned)__cvta_generic_to_shared(AsI);
    const unsigned bR = (unsigned)__cvta_generic_to_shared(BsR);
    const unsigned bI = (unsigned)__cvta_generic_to_shared(BsI);

    const int zb = blockIdx.z >> 3, zh = blockIdx.z & 7;
    const size_t Aoff = (size_t)zb*sAb + (size_t)zh*sAh;
    const size_t Boff = (size_t)zb*sBb + (size_t)zh*sBh;
    const size_t Coff = (size_t)zb*sCb + (size_t)zh*sCh;

    const int m0 = blockIdx.y * BM;
    const int n0 = blockIdx.x * BN;

    const int tid = threadIdx.x;
    const int tx = tid & 15, ty = tid >> 4;

    // loader mapping: k = tid&15, row = tid>>4 (16 rows/pass)
    const int kL = tid & 15;
    const int rL = tid >> 4;

    const float* gAr = Ar + Aoff + (size_t)(m0+rL)*lda + kL;
    const float* gAi = Ai + Aoff + (size_t)(m0+rL)*lda + kL;
    const float* gBr = Br + Boff + (size_t)(n0+rL)*ldb + kL;
    const float* gBi = Bi + Boff + (size_t)(n0+rL)*ldb + kL;

    const unsigned dAr = aR + kL*(APAD*4) + rL*4;
    const unsigned dAi = aI + kL*(APAD*4) + rL*4;
    const unsigned dBr = bR + kL*(BPAD*4) + rL*4;
    const unsigned dBi = bI + kL*(BPAD*4) + rL*4;

#define LOAD_NT(st, k0) do{                                              \
    const unsigned oA = (st)*A_STAGE_B, oB = (st)*B_STAGE_B;             \
    _Pragma("unroll")                                                    \
    for (int s=0;s<8;s++){                                               \
        cpa4(dAr + oA + s*64, gAr + (k0) + (size_t)(16*s)*lda);          \
        cpa4(dAi + oA + s*64, gAi + (k0) + (size_t)(16*s)*lda);          \
    }                                                                    \
    _Pragma("unroll")                                                    \
    for (int s=0;s<4;s++){                                               \
        cpa4(dBr + oB + s*64, gBr + (k0) + (size_t)(16*s)*ldb);          \
        cpa4(dBi + oB + s*64, gBi + (k0) + (size_t)(16*s)*ldb);          \
    }                                                                    \
    CP_COMMIT(); }while(0)

    u64t cr[4][4] = {}, ci[4][4] = {};

    const int NIT = K / BK;
    LOAD_NT(0, 0);
    if (NIT > 1) LOAD_NT(1, BK); else CP_COMMIT();

    int st = 0;
    for (int it = 0; it < NIT; it++){
        CP_WAIT1();
        __syncthreads();
        // issue loads for stage it+2 (overwrites stage it-1; safe after barrier)
        if (it + 2 < NIT){
            int stn = st + 2; if (stn >= 3) stn -= 3;
            LOAD_NT(stn, (it+2)*BK);
        } else {
            CP_COMMIT();
        }

        const unsigned bAr = aR + st*A_STAGE_B + ty*32;
        const unsigned bAi = aI + st*A_STAGE_B + ty*32;
        const float* BkR = BsR + st*B_STAGE_F;
        const float* BkI = BsI + st*B_STAGE_F;

        #pragma unroll
        for (int kk = 0; kk < BK; kk++){
            u64t ar[4], ai[4];
            const unsigned offk = kk*(APAD*4);
            lds2x64(ar[0], ar[1], bAr + offk);
            lds2x64(ar[2], ar[3], bAr + offk + 16);
            lds2x64(ai[0], ai[1], bAi + offk);
            lds2x64(ai[2], ai[3], bAi + offk + 16);

            const float4 b4r = *reinterpret_cast<const float4*>(BkR + kk*BPAD + (tx<<2));
            const float4 b4i = *reinterpret_cast<const float4*>(BkI + kk*BPAD + (tx<<2));
            const float brr[4] = {b4r.x,b4r.y,b4r.z,b4r.w};
            const float bii[4] = {b4i.x,b4i.y,b4i.z,b4i.w};
            #pragma unroll
            for (int j=0;j<4;j++){
                const u64t brd  = dup2(brr[j]);
                const u64t bid  = dup2(bii[j]);
                const u64t nbid = dup2(-bii[j]);
                #pragma unroll
                for (int ip=0;ip<4;ip++){
                    if (CONJB){
                        fma2(cr[ip][j], ar[ip], brd);
                        fma2(cr[ip][j], ai[ip], bid);
                        fma2(ci[ip][j], ai[ip], brd);
                        fma2(ci[ip][j], ar[ip], nbid);
                    } else {
                        fma2(cr[ip][j], ar[ip], brd);
                        fma2(cr[ip][j], ai[ip], nbid);
                        fma2(ci[ip][j], ar[ip], bid);
                        fma2(ci[ip][j], ai[ip], brd);
                    }
                }
            }
        }
        st++; if (st == 3) st = 0;
    }
#undef LOAD_NT

    float ss = 0.f, lm = 0.f;
    if (EPI == 2){
        ss = log1pf(expf(ssp[layer]));
        lm = log1pf(expf(lmp[layer]));
    }

    #pragma unroll
    for (int ip=0;ip<4;ip++){
        const int gm = m0 + ty*8 + ip*2;
        #pragma unroll
        for (int j=0;j<4;j++){
            const int gn = n0 + (tx<<2) + j;
            float2 vr = up2(cr[ip][j]);
            float2 vi = up2(ci[ip][j]);
            vr.x *= alpha; vr.y *= alpha; vi.x *= alpha; vi.y *= alpha;
            const size_t i0 = Coff + (size_t)gm*ldc + gn;
            const size_t i1 = i0 + ldc;
            if (EPI == 0){
                Cr[i0] = vr.x; Ci[i0] = vi.x;
                Cr[i1] = vr.y; Ci[i1] = vi.y;
            } else if (EPI == 1){
                Cr[i0] = vr.x + biasR[gn] + Cr[i0];
                Ci[i0] = vi.x + biasI[gn] + Ci[i0];
                Cr[i1] = vr.y + biasR[gn] + Cr[i1];
                Ci[i1] = vi.y + biasI[gn] + Ci[i1];
            } else {
                const float x0r = Xr[(size_t)gm*ldc + gn];
                const float x0i = Xi[(size_t)gm*ldc + gn];
                const float x1r = Xr[(size_t)(gm+1)*ldc + gn];
                const float x1i = Xi[(size_t)(gm+1)*ldc + gn];
                Cr[i0] = fmaxf(fmaf(ss, vr.x, x0r) - ss*lm, 0.f);
                Ci[i0] = fmaxf(fmaf(ss, vi.x, x0i), 0.f);
                Cr[i1] = fmaxf(fmaf(ss, vr.y, x1r) - ss*lm, 0.f);
                Ci[i1] = fmaxf(fmaf(ss, vi.y, x1i), 0.f);
            }
        }
    }
}

// ---- NN: C[m,n] = sum_k A[m,k] * B[k,n] ------------------------------------
__global__ __launch_bounds__(256, 2)
void cgemm_nn_kernel(const float* __restrict__ Ar, const float* __restrict__ Ai, int lda,
                     const float* __restrict__ Br, const float* __restrict__ Bi, int ldb,
                     float* __restrict__ Cr, float* __restrict__ Ci, int ldc,
                     int K,
                     size_t sAb, size_t sAh, size_t sBb, size_t sBh,
                     size_t sCb, size_t sCh)
{
    extern __shared__ float dsm[];
    float* AsR = dsm;
    float* AsI = AsR + 3*A_STAGE_F;
    float* BsR = AsI + 3*A_STAGE_F;
    float* BsI = BsR + 3*B_STAGE_F;
    const unsigned aR = (unsigned)__cvta_generic_to_shared(AsR);
    const unsigned aI = (unsigned)__cvta_generic_to_shared(AsI);
    const unsigned bR = (unsigned)__cvta_generic_to_shared(BsR);
    const unsigned bI = (unsigned)__cvta_generic_to_shared(BsI);

    const int zb = blockIdx.z >> 3, zh = blockIdx.z & 7;
    const size_t Aoff = (size_t)zb*sAb + (size_t)zh*sAh;
    const size_t Boff = (size_t)zb*sBb + (size_t)zh*sBh;
    const size_t Coff = (size_t)zb*sCb + (size_t)zh*sCh;

    const int m0 = blockIdx.y * BM;
    const int n0 = blockIdx.x * BN;

    const int tid = threadIdx.x;
    const int tx = tid & 15, ty = tid >> 4;

    const int kL = tid & 15;
    const int rL = tid >> 4;
    const int ncB = (tid & 15) << 2;   // 0..60
    const int kB  = tid >> 4;          // 0..15

    const float* gAr = Ar + Aoff + (size_t)(m0+rL)*lda + kL;
    const float* gAi = Ai + Aoff + (size_t)(m0+rL)*lda + kL;
    const float* gBr = Br + Boff + (size_t)kB*ldb + n0 + ncB;
    const float* gBi = Bi + Boff + (size_t)kB*ldb + n0 + ncB;

    const unsigned dAr = aR + kL*(APAD*4) + rL*4;
    const unsigned dAi = aI + kL*(APAD*4) + rL*4;
    const unsigned dBr = bR + kB*(BPAD*4) + ncB*4;
    const unsigned dBi = bI + kB*(BPAD*4) + ncB*4;

#define LOAD_NN(st, k0) do{                                              \
    const unsigned oA = (st)*A_STAGE_B, oB = (st)*B_STAGE_B;             \
    _Pragma("unroll")                                                    \
    for (int s=0;s<8;s++){                                               \
        cpa4(dAr + oA + s*64, gAr + (k0) + (size_t)(16*s)*lda);          \
        cpa4(dAi + oA + s*64, gAi + (k0) + (size_t)(16*s)*lda);          \
    }                                                                    \
    cpa16(dBr + oB, gBr + (size_t)(k0)*ldb);                             \
    cpa16(dBi + oB, gBi + (size_t)(k0)*ldb);                             \
    CP_COMMIT(); }while(0)

    u64t cr[4][4] = {}, ci[4][4] = {};

    const int NIT = K / BK;
    LOAD_NN(0, 0);
    if (NIT > 1) LOAD_NN(1, BK); else CP_COMMIT();

    int st = 0;
    for (int it = 0; it < NIT; it++){
        CP_WAIT1();
        __syncthreads();
        if (it + 2 < NIT){
            int stn = st + 2; if (stn >= 3) stn -= 3;
            LOAD_NN(stn, (it+2)*BK);
        } else {
            CP_COMMIT();
        }

        const unsigned bAr = aR + st*A_STAGE_B + ty*32;
        const unsigned bAi = aI + st*A_STAGE_B + ty*32;
        const float* BkR = BsR + st*B_STAGE_F;
        const float* BkI = BsI + st*B_STAGE_F;

        #pragma unroll
        for (int kk = 0; kk < BK; kk++){
            u64t ar[4], ai[4];
            const unsigned offk = kk*(APAD*4);
            lds2x64(ar[0], ar[1], bAr + offk);
            lds2x64(ar[2], ar[3], bAr + offk + 16);
            lds2x64(ai[0], ai[1], bAi + offk);
            lds2x64(ai[2], ai[3], bAi + offk + 16);

            const float4 b4r = *reinterpret_cast<const float4*>(BkR + kk*BPAD + (tx<<2));
            const float4 b4i = *reinterpret_cast<const float4*>(BkI + kk*BPAD + (tx<<2));
            const float brr[4] = {b4r.x,b4r.y,b4r.z,b4r.w};
            const float bii[4] = {b4i.x,b4i.y,b4i.z,b4i.w};
            #pragma unroll
            for (int j=0;j<4;j++){
                const u64t brd  = dup2(brr[j]);
                const u64t bid  = dup2(bii[j]);
                const u64t nbid = dup2(-bii[j]);
                #pragma unroll
                for (int ip=0;ip<4;ip++){
                    fma2(cr[ip][j], ar[ip], brd);
                    fma2(cr[ip][j], ai[ip], nbid);
                    fma2(ci[ip][j], ar[ip], bid);
                    fma2(ci[ip][j], ai[ip], brd);
                }
            }
        }
        st++; if (st == 3) st = 0;
    }
#undef LOAD_NN

    #pragma unroll
    for (int ip=0;ip<4;ip++){
        const int gm = m0 + ty*8 + ip*2;
        #pragma unroll
        for (int j=0;j<4;j++){
            const int gn = n0 + (tx<<2) + j;
            const float2 vr = up2(cr[ip][j]);
            const float2 vi = up2(ci[ip][j]);
            const size_t i0 = Coff + (size_t)gm*ldc + gn;
            const size_t i1 = i0 + ldc;
            Cr[i0] = vr.x; Ci[i0] = vi.x;
            Cr[i1] = vr.y; Ci[i1] = vi.y;
        }
    }
}

// ---------------- launch ----------------------------------------------------
extern "C" void kernel_launch(void* const* d_in, const int* in_sizes, int n_in,
                              void* d_out, int out_size)
{
    const float* x_real   = (const float*)d_in[0];
    const float* x_imag   = (const float*)d_in[1];
    const float* ln1_g_r  = (const float*)d_in[2];
    const float* ln1_b_r  = (const float*)d_in[3];
    const float* ln1_g_i  = (const float*)d_in[4];
    const float* ln1_b_i  = (const float*)d_in[5];
    const float* ln2_g_r  = (const float*)d_in[6];
    const float* ln2_b_r  = (const float*)d_in[7];
    const float* ln2_g_i  = (const float*)d_in[8];
    const float* ln2_b_i  = (const float*)d_in[9];
    const float* qkv_w_r  = (const float*)d_in[10];
    const float* qkv_w_i  = (const float*)d_in[11];
    const float* out_w_r  = (const float*)d_in[12];
    const float* out_w_i  = (const float*)d_in[13];
    const float* out_b_r  = (const float*)d_in[14];
    const float* out_b_i  = (const float*)d_in[15];
    const float* ff_w_r   = (const float*)d_in[16];
    const float* ff_w_i   = (const float*)d_in[17];
    const float* step_sz  = (const float*)d_in[18];
    const float* lambd    = (const float*)d_in[19];

    float *xr,*xi,*xnr,*xni,*wr,*wi,*ar,*ai,*dr,*di;
    cudaGetSymbolAddress((void**)&xr,  g_x_r);
    cudaGetSymbolAddress((void**)&xi,  g_x_i);
    cudaGetSymbolAddress((void**)&xnr, g_xn_r);
    cudaGetSymbolAddress((void**)&xni, g_xn_i);
    cudaGetSymbolAddress((void**)&wr,  g_w_r);
    cudaGetSymbolAddress((void**)&wi,  g_w_i);
    cudaGetSymbolAddress((void**)&ar,  g_at_r);
    cudaGetSymbolAddress((void**)&ai,  g_at_i);
    cudaGetSymbolAddress((void**)&dr,  g_d_r);
    cudaGetSymbolAddress((void**)&di,  g_d_i);

    cudaFuncSetAttribute(cgemm_nt_kernel<0,false>, cudaFuncAttributeMaxDynamicSharedMemorySize, SMEM_BYTES);
    cudaFuncSetAttribute(cgemm_nt_kernel<0,true >, cudaFuncAttributeMaxDynamicSharedMemorySize, SMEM_BYTES);
    cudaFuncSetAttribute(cgemm_nt_kernel<1,false>, cudaFuncAttributeMaxDynamicSharedMemorySize, SMEM_BYTES);
    cudaFuncSetAttribute(cgemm_nt_kernel<2,false>, cudaFuncAttributeMaxDynamicSharedMemorySize, SMEM_BYTES);
    cudaFuncSetAttribute(cgemm_nn_kernel,          cudaFuncAttributeMaxDynamicSharedMemorySize, SMEM_BYTES);

    const int NE = ROWS*DIM;
    copy_in_kernel<<<(NE+255)/256, 256>>>(x_real, x_imag, xr, xi, NE);

    const size_t sRow = (size_t)NN*DIM;
    const size_t sNN  = (size_t)NN*NN;

    for (int l = 0; l < DEPTH; l++){
        const size_t wo = (size_t)l*DIM*DIM;
        const size_t po = (size_t)l*DIM;

        // LN1
        cln_kernel<<<ROWS,128>>>(xr,xi, ln1_g_r+po, ln1_b_r+po, ln1_g_i+po, ln1_b_i+po, xnr,xni);
        // QKV: w = xn @ Wqkv^T
        cgemm_nt_kernel<0,false><<<dim3(8,16,1),256,SMEM_BYTES>>>(
            xnr,xni,DIM, qkv_w_r+wo,qkv_w_i+wo,DIM, wr,wi,DIM, DIM, 1.0f,
            0,0,0,0,0,0, nullptr,nullptr, nullptr,nullptr, nullptr,nullptr, 0);
        // dots[b,h] = scale * w @ conj(w)^T  (K=64)
        cgemm_nt_kernel<0,true><<<dim3(8,4,32),256,SMEM_BYTES>>>(
            wr,wi,DIM, wr,wi,DIM, dr,di,NN, DH, ATT_SCALE,
            sRow,(size_t)DH, sRow,(size_t)DH, (size_t)8*sNN, sNN,
            nullptr,nullptr, nullptr,nullptr, nullptr,nullptr, 0);
        // magnitude softmax (warp per row)
        csoftmax_kernel<<<BB*HEADS*NN/8,256>>>(dr,di);
        // att = attn @ w
        cgemm_nn_kernel<<<dim3(1,4,32),256,SMEM_BYTES>>>(
            dr,di,NN, wr,wi,DIM, ar,ai,DIM, NN,
            (size_t)8*sNN, sNN, sRow,(size_t)DH, sRow,(size_t)DH);
        // x = att @ Wout^T + bout + x
        cgemm_nt_kernel<1,false><<<dim3(8,16,1),256,SMEM_BYTES>>>(
            ar,ai,DIM, out_w_r+wo,out_w_i+wo,DIM, xr,xi,DIM, DIM, 1.0f,
            0,0,0,0,0,0, out_b_r+po,out_b_i+po, nullptr,nullptr, nullptr,nullptr, 0);
        // LN2
        cln_kernel<<<ROWS,128>>>(xr,xi, ln2_g_r+po, ln2_b_r+po, ln2_g_i+po, ln2_b_i+po, xnr,xni);
        // x = crelu(xn + ss*(xn @ Wff^T) - ss*lm)
        cgemm_nt_kernel<2,false><<<dim3(8,16,1),256,SMEM_BYTES>>>(
            xnr,xni,DIM, ff_w_r+wo,ff_w_i+wo,DIM, xr,xi,DIM, DIM, 1.0f,
            0,0,0,0,0,0, nullptr,nullptr, xnr,xni, step_sz,lambd, l);
    }

    copy_out_kernel<<<(NE+255)/256, 256>>>(xr, xi, (float*)d_out, NE);
}

// round 5
// speedup vs baseline: 1.1492x; 1.0007x over previous
#include <cuda_runtime.h>
#include <math.h>

#define BB 4
#define NN 512
#define DIM 512
#define HEADS 8
#define DH 64
#define DEPTH 4
#define ROWS (BB*NN)          // 2048
#define ATT_SCALE 0.125f
#define LN_EPS 1e-5f

// ---------------- scratch (static device memory; no allocation) -------------
__device__ float g_x_r [ROWS*DIM];
__device__ float g_x_i [ROWS*DIM];
__device__ float g_xn_r[ROWS*DIM];
__device__ float g_xn_i[ROWS*DIM];
__device__ float g_w_r [ROWS*DIM];
__device__ float g_w_i [ROWS*DIM];
__device__ float g_at_r[ROWS*DIM];
__device__ float g_at_i[ROWS*DIM];
__device__ float g_d_r [BB*HEADS*NN*NN];
__device__ float g_d_i [BB*HEADS*NN*NN];

// ---------------- f32x2 / async helpers -------------------------------------
typedef unsigned long long u64t;

__device__ __forceinline__ u64t dup2(float s){
    u64t r; asm("mov.b64 %0, {%1, %1};" : "=l"(r) : "f"(s)); return r;
}
__device__ __forceinline__ void fma2(u64t &d, u64t a, u64t b){
    asm("fma.rn.f32x2 %0, %1, %2, %0;" : "+l"(d) : "l"(a), "l"(b));
}
__device__ __forceinline__ float2 up2(u64t v){
    float2 f; asm("mov.b64 {%0, %1}, %2;" : "=f"(f.x), "=f"(f.y) : "l"(v)); return f;
}
__device__ __forceinline__ void cpa4(unsigned dst, const float* src){
    asm volatile("cp.async.ca.shared.global [%0], [%1], 4;" :: "r"(dst), "l"(src));
}
__device__ __forceinline__ void cpa16(unsigned dst, const float* src){
    asm volatile("cp.async.cg.shared.global [%0], [%1], 16;" :: "r"(dst), "l"(src));
}
#define CP_COMMIT() asm volatile("cp.async.commit_group;")
#define CP_WAIT1()  asm volatile("cp.async.wait_group 1;")

__device__ __forceinline__ float warp_sum(float v){
    #pragma unroll
    for (int o=16;o;o>>=1) v += __shfl_xor_sync(0xffffffffu, v, o);
    return v;
}
__device__ __forceinline__ float warp_max(float v){
    #pragma unroll
    for (int o=16;o;o>>=1) v = fmaxf(v, __shfl_xor_sync(0xffffffffu, v, o));
    return v;
}

// ---------------- copy in / out ---------------------------------------------
__global__ void copy_in_kernel(const float* __restrict__ a, const float* __restrict__ b,
                               float* __restrict__ xr, float* __restrict__ xi, int n){
    int i = blockIdx.x*blockDim.x + threadIdx.x;
    if (i < n){ xr[i] = a[i]; xi[i] = b[i]; }
}
__global__ void copy_out_kernel(const float* __restrict__ xr, const float* __restrict__ xi,
                                float* __restrict__ out, int n){
    int i = blockIdx.x*blockDim.x + threadIdx.x;
    if (i < n){ out[i] = xr[i]; out[n+i] = xi[i]; }
}

// ---------------- complex LayerNorm (per row of 512) ------------------------
__global__ __launch_bounds__(128)
void cln_kernel(const float* __restrict__ xr, const float* __restrict__ xi,
                const float* __restrict__ gr, const float* __restrict__ br,
                const float* __restrict__ gi, const float* __restrict__ bi,
                float* __restrict__ outr, float* __restrict__ outi)
{
    const int row = blockIdx.x;
    const int t   = threadIdx.x;
    const float4 vr = reinterpret_cast<const float4*>(xr + (size_t)row*DIM)[t];
    const float4 vi = reinterpret_cast<const float4*>(xi + (size_t)row*DIM)[t];

    float sr  = vr.x+vr.y+vr.z+vr.w;
    float s2r = vr.x*vr.x+vr.y*vr.y+vr.z*vr.z+vr.w*vr.w;
    float si  = vi.x+vi.y+vi.z+vi.w;
    float s2i = vi.x*vi.x+vi.y*vi.y+vi.z*vi.z+vi.w*vi.w;

    sr = warp_sum(sr); s2r = warp_sum(s2r); si = warp_sum(si); s2i = warp_sum(s2i);

    __shared__ float red[4][4];
    const int wid = t >> 5, lane = t & 31;
    if (lane == 0){ red[wid][0]=sr; red[wid][1]=s2r; red[wid][2]=si; red[wid][3]=s2i; }
    __syncthreads();
    float tr=0,t2r=0,ti=0,t2i=0;
    #pragma unroll
    for (int w=0; w<4; w++){ tr+=red[w][0]; t2r+=red[w][1]; ti+=red[w][2]; t2i+=red[w][3]; }

    const float inv = 1.0f/DIM;
    const float mr = tr*inv,  vvr = t2r*inv - mr*mr;
    const float mi = ti*inv,  vvi = t2i*inv - mi*mi;
    const float rr = rsqrtf(vvr + LN_EPS);
    const float ri = rsqrtf(vvi + LN_EPS);

    const float4 g4r = reinterpret_cast<const float4*>(gr)[t];
    const float4 b4r = reinterpret_cast<const float4*>(br)[t];
    const float4 g4i = reinterpret_cast<const float4*>(gi)[t];
    const float4 b4i = reinterpret_cast<const float4*>(bi)[t];

    float4 orr, oii;
    orr.x = (vr.x-mr)*rr*g4r.x + b4r.x;  oii.x = (vi.x-mi)*ri*g4i.x + b4i.x;
    orr.y = (vr.y-mr)*rr*g4r.y + b4r.y;  oii.y = (vi.y-mi)*ri*g4i.y + b4i.y;
    orr.z = (vr.z-mr)*rr*g4r.z + b4r.z;  oii.z = (vi.z-mi)*ri*g4i.z + b4i.z;
    orr.w = (vr.w-mr)*rr*g4r.w + b4r.w;  oii.w = (vi.w-mi)*ri*g4i.w + b4i.w;
    reinterpret_cast<float4*>(outr + (size_t)row*DIM)[t] = orr;
    reinterpret_cast<float4*>(outi + (size_t)row*DIM)[t] = oii;
}

// ---------------- magnitude softmax: one warp per row, no barriers ----------
__global__ __launch_bounds__(256)
void csoftmax_kernel(float* __restrict__ zr, float* __restrict__ zi)
{
    const int wid = threadIdx.x >> 5, lane = threadIdx.x & 31;
    const size_t row = (size_t)blockIdx.x*8 + wid;
    float* pr = zr + row*NN;
    float* pi = zi + row*NN;

    float4 vr[4], vi[4];
    #pragma unroll
    for (int u=0;u<4;u++){
        vr[u] = reinterpret_cast<const float4*>(pr)[lane + 32*u];
        vi[u] = reinterpret_cast<const float4*>(pi)[lane + 32*u];
    }
    float m[16];
    #pragma unroll
    for (int u=0;u<4;u++){
        m[4*u+0] = sqrtf(vr[u].x*vr[u].x + vi[u].x*vi[u].x);
        m[4*u+1] = sqrtf(vr[u].y*vr[u].y + vi[u].y*vi[u].y);
        m[4*u+2] = sqrtf(vr[u].z*vr[u].z + vi[u].z*vi[u].z);
        m[4*u+3] = sqrtf(vr[u].w*vr[u].w + vi[u].w*vi[u].w);
    }
    float mx = m[0];
    #pragma unroll
    for (int e=1;e<16;e++) mx = fmaxf(mx, m[e]);
    mx = warp_max(mx);

    float ex[16]; float s = 0.f;
    #pragma unroll
    for (int e=0;e<16;e++){ ex[e] = __expf(m[e] - mx); s += ex[e]; }
    s = warp_sum(s);
    const float inv = 1.0f / s;

    #pragma unroll
    for (int u=0;u<4;u++){
        float sc;
        sc = (m[4*u+0] > 0.f) ? ex[4*u+0]*inv/m[4*u+0] : 0.f;
        if (m[4*u+0] > 0.f){ vr[u].x *= sc; vi[u].x *= sc; } else { vr[u].x = ex[4*u+0]*inv; vi[u].x = 0.f; }
        sc = (m[4*u+1] > 0.f) ? ex[4*u+1]*inv/m[4*u+1] : 0.f;
        if (m[4*u+1] > 0.f){ vr[u].y *= sc; vi[u].y *= sc; } else { vr[u].y = ex[4*u+1]*inv; vi[u].y = 0.f; }
        sc = (m[4*u+2] > 0.f) ? ex[4*u+2]*inv/m[4*u+2] : 0.f;
        if (m[4*u+2] > 0.f){ vr[u].z *= sc; vi[u].z *= sc; } else { vr[u].z = ex[4*u+2]*inv; vi[u].z = 0.f; }
        sc = (m[4*u+3] > 0.f) ? ex[4*u+3]*inv/m[4*u+3] : 0.f;
        if (m[4*u+3] > 0.f){ vr[u].w *= sc; vi[u].w *= sc; } else { vr[u].w = ex[4*u+3]*inv; vi[u].w = 0.f; }
        reinterpret_cast<float4*>(pr)[lane + 32*u] = vr[u];
        reinterpret_cast<float4*>(pi)[lane + 32*u] = vi[u];
    }
}

// ======================= f32x2 complex GEMM (cp.async, 3-stage) ==============
#define BM 128
#define BN 64
#define BK 16
#define APAD 132           // row stride floats (528B, 16B aligned)
#define BPAD 68            // 272B, 16B aligned
#define A_STAGE_F (BK*APAD)      // 2112 floats
#define B_STAGE_F (BK*BPAD)      // 1088 floats
#define A_STAGE_B (A_STAGE_F*4)  // 8448 bytes
#define B_STAGE_B (B_STAGE_F*4)  // 4352 bytes
#define SMEM_BYTES (3*(2*A_STAGE_B + 2*B_STAGE_B))   // 76800

// compute body shared by NT/NN (reads A pairs via plain C++ 16B loads so the
// compiler can pipeline LDS across kk; no volatile fences in the hot loop)
template<bool CONJB>
__device__ __forceinline__ void gemm_body(const float* __restrict__ Ast_r,
                                          const float* __restrict__ Ast_i,
                                          const float* __restrict__ Bst_r,
                                          const float* __restrict__ Bst_i,
                                          int ty, int tx,
                                          u64t cr[4][4], u64t ci[4][4])
{
    const float* ArBase = Ast_r + ty*8;
    const float* AiBase = Ast_i + ty*8;
    #pragma unroll
    for (int kk = 0; kk < BK; kk++){
        u64t ar[4], ai[4];
        const ulonglong2 arл0 = *reinterpret_cast<const ulonglong2*>(ArBase + kk*APAD);
        const ulonglong2 arл1 = *reinterpret_cast<const ulonglong2*>(ArBase + kk*APAD + 4);
        const ulonglong2 aiл0 = *reinterpret_cast<const ulonglong2*>(AiBase + kk*APAD);
        const ulonglong2 aiл1 = *reinterpret_cast<const ulonglong2*>(AiBase + kk*APAD + 4);
        ar[0] = arл0.x; ar[1] = arл0.y; ar[2] = arл1.x; ar[3] = arл1.y;
        ai[0] = aiл0.x; ai[1] = aiл0.y; ai[2] = aiл1.x; ai[3] = aiл1.y;

        const float4 b4r = *reinterpret_cast<const float4*>(Bst_r + kk*BPAD + (tx<<2));
        const float4 b4i = *reinterpret_cast<const float4*>(Bst_i + kk*BPAD + (tx<<2));
        const float brr[4] = {b4r.x,b4r.y,b4r.z,b4r.w};
        const float bii[4] = {b4i.x,b4i.y,b4i.z,b4i.w};
        #pragma unroll
        for (int j=0;j<4;j++){
            const u64t brd  = dup2(brr[j]);
            const u64t bid  = dup2(bii[j]);
            const u64t nbid = dup2(-bii[j]);
            #pragma unroll
            for (int ip=0;ip<4;ip++){
                if (CONJB){
                    fma2(cr[ip][j], ar[ip], brd);
                    fma2(cr[ip][j], ai[ip], bid);
                    fma2(ci[ip][j], ai[ip], brd);
                    fma2(ci[ip][j], ar[ip], nbid);
                } else {
                    fma2(cr[ip][j], ar[ip], brd);
                    fma2(cr[ip][j], ai[ip], nbid);
                    fma2(ci[ip][j], ar[ip], bid);
                    fma2(ci[ip][j], ai[ip], brd);
                }
            }
        }
    }
}

// ---- NT: C[m,n] = alpha * sum_k A[m,k] * (conj?) B[n,k] --------------------
template<int EPI, bool CONJB>
__global__ __launch_bounds__(256, 2)
void cgemm_nt_kernel(const float* __restrict__ Ar, const float* __restrict__ Ai, int lda,
                     const float* __restrict__ Br, const float* __restrict__ Bi, int ldb,
                     float* Cr, float* Ci, int ldc,
                     int K, float alpha,
                     size_t sAb, size_t sAh, size_t sBb, size_t sBh,
                     size_t sCb, size_t sCh,
                     const float* __restrict__ biasR, const float* __restrict__ biasI,
                     const float* __restrict__ Xr, const float* __restrict__ Xi,
                     const float* __restrict__ ssp, const float* __restrict__ lmp, int layer)
{
    extern __shared__ float dsm[];
    float* AsR = dsm;
    float* AsI = AsR + 3*A_STAGE_F;
    float* BsR = AsI + 3*A_STAGE_F;
    float* BsI = BsR + 3*B_STAGE_F;
    const unsigned aR = (unsigned)__cvta_generic_to_shared(AsR);
    const unsigned aI = (unsigned)__cvta_generic_to_shared(AsI);
    const unsigned bR = (unsigned)__cvta_generic_to_shared(BsR);
    const unsigned bI = (unsigned)__cvta_generic_to_shared(BsI);

    const int zb = blockIdx.z >> 3, zh = blockIdx.z & 7;
    const size_t Aoff = (size_t)zb*sAb + (size_t)zh*sAh;
    const size_t Boff = (size_t)zb*sBb + (size_t)zh*sBh;
    const size_t Coff = (size_t)zb*sCb + (size_t)zh*sCh;

    const int m0 = blockIdx.y * BM;
    const int n0 = blockIdx.x * BN;

    const int tid = threadIdx.x;
    const int tx = tid & 15, ty = tid >> 4;

    const int kL = tid & 15;
    const int rL = tid >> 4;

    const float* gAr = Ar + Aoff + (size_t)(m0+rL)*lda + kL;
    const float* gAi = Ai + Aoff + (size_t)(m0+rL)*lda + kL;
    const float* gBr = Br + Boff + (size_t)(n0+rL)*ldb + kL;
    const float* gBi = Bi + Boff + (size_t)(n0+rL)*ldb + kL;

    const unsigned dAr = aR + kL*(APAD*4) + rL*4;
    const unsigned dAi = aI + kL*(APAD*4) + rL*4;
    const unsigned dBr = bR + kL*(BPAD*4) + rL*4;
    const unsigned dBi = bI + kL*(BPAD*4) + rL*4;

#define LOAD_NT(st, k0) do{                                              \
    const unsigned oA = (st)*A_STAGE_B, oB = (st)*B_STAGE_B;             \
    _Pragma("unroll")                                                    \
    for (int s=0;s<8;s++){                                               \
        cpa4(dAr + oA + s*64, gAr + (k0) + (size_t)(16*s)*lda);          \
        cpa4(dAi + oA + s*64, gAi + (k0) + (size_t)(16*s)*lda);          \
    }                                                                    \
    _Pragma("unroll")                                                    \
    for (int s=0;s<4;s++){                                               \
        cpa4(dBr + oB + s*64, gBr + (k0) + (size_t)(16*s)*ldb);          \
        cpa4(dBi + oB + s*64, gBi + (k0) + (size_t)(16*s)*ldb);          \
    }                                                                    \
    CP_COMMIT(); }while(0)

    u64t cr[4][4] = {}, ci[4][4] = {};

    const int NIT = K / BK;
    LOAD_NT(0, 0);
    if (NIT > 1) LOAD_NT(1, BK); else CP_COMMIT();

    int st = 0;
    for (int it = 0; it < NIT; it++){
        CP_WAIT1();
        __syncthreads();
        if (it + 2 < NIT){
            int stn = st + 2; if (stn >= 3) stn -= 3;
            LOAD_NT(stn, (it+2)*BK);
        } else {
            CP_COMMIT();
        }

        gemm_body<CONJB>(AsR + st*A_STAGE_F, AsI + st*A_STAGE_F,
                         BsR + st*B_STAGE_F, BsI + st*B_STAGE_F, ty, tx, cr, ci);
        st++; if (st == 3) st = 0;
    }
#undef LOAD_NT

    float ss = 0.f, lm = 0.f;
    if (EPI == 2){
        ss = log1pf(expf(ssp[layer]));
        lm = log1pf(expf(lmp[layer]));
    }

    #pragma unroll
    for (int ip=0;ip<4;ip++){
        const int gm = m0 + ty*8 + ip*2;
        #pragma unroll
        for (int j=0;j<4;j++){
            const int gn = n0 + (tx<<2) + j;
            float2 vr = up2(cr[ip][j]);
            float2 vi = up2(ci[ip][j]);
            vr.x *= alpha; vr.y *= alpha; vi.x *= alpha; vi.y *= alpha;
            const size_t i0 = Coff + (size_t)gm*ldc + gn;
            const size_t i1 = i0 + ldc;
            if (EPI == 0){
                Cr[i0] = vr.x; Ci[i0] = vi.x;
                Cr[i1] = vr.y; Ci[i1] = vi.y;
            } else if (EPI == 1){
                Cr[i0] = vr.x + biasR[gn] + Cr[i0];
                Ci[i0] = vi.x + biasI[gn] + Ci[i0];
                Cr[i1] = vr.y + biasR[gn] + Cr[i1];
                Ci[i1] = vi.y + biasI[gn] + Ci[i1];
            } else {
                const float x0r = Xr[(size_t)gm*ldc + gn];
                const float x0i = Xi[(size_t)gm*ldc + gn];
                const float x1r = Xr[(size_t)(gm+1)*ldc + gn];
                const float x1i = Xi[(size_t)(gm+1)*ldc + gn];
                Cr[i0] = fmaxf(fmaf(ss, vr.x, x0r) - ss*lm, 0.f);
                Ci[i0] = fmaxf(fmaf(ss, vi.x, x0i), 0.f);
                Cr[i1] = fmaxf(fmaf(ss, vr.y, x1r) - ss*lm, 0.f);
                Ci[i1] = fmaxf(fmaf(ss, vi.y, x1i), 0.f);
            }
        }
    }
}

// ---- NN: C[m,n] = sum_k A[m,k] * B[k,n] ------------------------------------
__global__ __launch_bounds__(256, 2)
void cgemm_nn_kernel(const float* __restrict__ Ar, const float* __restrict__ Ai, int lda,
                     const float* __restrict__ Br, const float* __restrict__ Bi, int ldb,
                     float* __restrict__ Cr, float* __restrict__ Ci, int ldc,
                     int K,
                     size_t sAb, size_t sAh, size_t sBb, size_t sBh,
                     size_t sCb, size_t sCh)
{
    extern __shared__ float dsm[];
    float* AsR = dsm;
    float* AsI = AsR + 3*A_STAGE_F;
    float* BsR = AsI + 3*A_STAGE_F;
    float* BsI = BsR + 3*B_STAGE_F;
    const unsigned aR = (unsigned)__cvta_generic_to_shared(AsR);
    const unsigned aI = (unsigned)__cvta_generic_to_shared(AsI);
    const unsigned bR = (unsigned)__cvta_generic_to_shared(BsR);
    const unsigned bI = (unsigned)__cvta_generic_to_shared(BsI);

    const int zb = blockIdx.z >> 3, zh = blockIdx.z & 7;
    const size_t Aoff = (size_t)zb*sAb + (size_t)zh*sAh;
    const size_t Boff = (size_t)zb*sBb + (size_t)zh*sBh;
    const size_t Coff = (size_t)zb*sCb + (size_t)zh*sCh;

    const int m0 = blockIdx.y * BM;
    const int n0 = blockIdx.x * BN;

    const int tid = threadIdx.x;
    const int tx = tid & 15, ty = tid >> 4;

    const int kL = tid & 15;
    const int rL = tid >> 4;
    const int ncB = (tid & 15) << 2;   // 0..60
    const int kB  = tid >> 4;          // 0..15

    const float* gAr = Ar + Aoff + (size_t)(m0+rL)*lda + kL;
    const float* gAi = Ai + Aoff + (size_t)(m0+rL)*lda + kL;
    const float* gBr = Br + Boff + (size_t)kB*ldb + n0 + ncB;
    const float* gBi = Bi + Boff + (size_t)kB*ldb + n0 + ncB;

    const unsigned dAr = aR + kL*(APAD*4) + rL*4;
    const unsigned dAi = aI + kL*(APAD*4) + rL*4;
    const unsigned dBr = bR + kB*(BPAD*4) + ncB*4;
    const unsigned dBi = bI + kB*(BPAD*4) + ncB*4;

#define LOAD_NN(st, k0) do{                                              \
    const unsigned oA = (st)*A_STAGE_B, oB = (st)*B_STAGE_B;             \
    _Pragma("unroll")                                                    \
    for (int s=0;s<8;s++){                                               \
        cpa4(dAr + oA + s*64, gAr + (k0) + (size_t)(16*s)*lda);          \
        cpa4(dAi + oA + s*64, gAi + (k0) + (size_t)(16*s)*lda);          \
    }                                                                    \
    cpa16(dBr + oB, gBr + (size_t)(k0)*ldb);                             \
    cpa16(dBi + oB, gBi + (size_t)(k0)*ldb);                             \
    CP_COMMIT(); }while(0)

    u64t cr[4][4] = {}, ci[4][4] = {};

    const int NIT = K / BK;
    LOAD_NN(0, 0);
    if (NIT > 1) LOAD_NN(1, BK); else CP_COMMIT();

    int st = 0;
    for (int it = 0; it < NIT; it++){
        CP_WAIT1();
        __syncthreads();
        if (it + 2 < NIT){
            int stn = st + 2; if (stn >= 3) stn -= 3;
            LOAD_NN(stn, (it+2)*BK);
        } else {
            CP_COMMIT();
        }

        gemm_body<false>(AsR + st*A_STAGE_F, AsI + st*A_STAGE_F,
                         BsR + st*B_STAGE_F, BsI + st*B_STAGE_F, ty, tx, cr, ci);
        st++; if (st == 3) st = 0;
    }
#undef LOAD_NN

    #pragma unroll
    for (int ip=0;ip<4;ip++){
        const int gm = m0 + ty*8 + ip*2;
        #pragma unroll
        for (int j=0;j<4;j++){
            const int gn = n0 + (tx<<2) + j;
            const float2 vr = up2(cr[ip][j]);
            const float2 vi = up2(ci[ip][j]);
            const size_t i0 = Coff + (size_t)gm*ldc + gn;
            const size_t i1 = i0 + ldc;
            Cr[i0] = vr.x; Ci[i0] = vi.x;
            Cr[i1] = vr.y; Ci[i1] = vi.y;
        }
    }
}

// ---------------- launch ----------------------------------------------------
extern "C" void kernel_launch(void* const* d_in, const int* in_sizes, int n_in,
                              void* d_out, int out_size)
{
    const float* x_real   = (const float*)d_in[0];
    const float* x_imag   = (const float*)d_in[1];
    const float* ln1_g_r  = (const float*)d_in[2];
    const float* ln1_b_r  = (const float*)d_in[3];
    const float* ln1_g_i  = (const float*)d_in[4];
    const float* ln1_b_i  = (const float*)d_in[5];
    const float* ln2_g_r  = (const float*)d_in[6];
    const float* ln2_b_r  = (const float*)d_in[7];
    const float* ln2_g_i  = (const float*)d_in[8];
    const float* ln2_b_i  = (const float*)d_in[9];
    const float* qkv_w_r  = (const float*)d_in[10];
    const float* qkv_w_i  = (const float*)d_in[11];
    const float* out_w_r  = (const float*)d_in[12];
    const float* out_w_i  = (const float*)d_in[13];
    const float* out_b_r  = (const float*)d_in[14];
    const float* out_b_i  = (const float*)d_in[15];
    const float* ff_w_r   = (const float*)d_in[16];
    const float* ff_w_i   = (const float*)d_in[17];
    const float* step_sz  = (const float*)d_in[18];
    const float* lambd    = (const float*)d_in[19];

    float *xr,*xi,*xnr,*xni,*wr,*wi,*ar,*ai,*dr,*di;
    cudaGetSymbolAddress((void**)&xr,  g_x_r);
    cudaGetSymbolAddress((void**)&xi,  g_x_i);
    cudaGetSymbolAddress((void**)&xnr, g_xn_r);
    cudaGetSymbolAddress((void**)&xni, g_xn_i);
    cudaGetSymbolAddress((void**)&wr,  g_w_r);
    cudaGetSymbolAddress((void**)&wi,  g_w_i);
    cudaGetSymbolAddress((void**)&ar,  g_at_r);
    cudaGetSymbolAddress((void**)&ai,  g_at_i);
    cudaGetSymbolAddress((void**)&dr,  g_d_r);
    cudaGetSymbolAddress((void**)&di,  g_d_i);

    cudaFuncSetAttribute(cgemm_nt_kernel<0,false>, cudaFuncAttributeMaxDynamicSharedMemorySize, SMEM_BYTES);
    cudaFuncSetAttribute(cgemm_nt_kernel<0,true >, cudaFuncAttributeMaxDynamicSharedMemorySize, SMEM_BYTES);
    cudaFuncSetAttribute(cgemm_nt_kernel<1,false>, cudaFuncAttributeMaxDynamicSharedMemorySize, SMEM_BYTES);
    cudaFuncSetAttribute(cgemm_nt_kernel<2,false>, cudaFuncAttributeMaxDynamicSharedMemorySize, SMEM_BYTES);
    cudaFuncSetAttribute(cgemm_nn_kernel,          cudaFuncAttributeMaxDynamicSharedMemorySize, SMEM_BYTES);

    const int NE = ROWS*DIM;
    copy_in_kernel<<<(NE+255)/256, 256>>>(x_real, x_imag, xr, xi, NE);

    const size_t sRow = (size_t)NN*DIM;
    const size_t sNN  = (size_t)NN*NN;

    for (int l = 0; l < DEPTH; l++){
        const size_t wo = (size_t)l*DIM*DIM;
        const size_t po = (size_t)l*DIM;

        // LN1
        cln_kernel<<<ROWS,128>>>(xr,xi, ln1_g_r+po, ln1_b_r+po, ln1_g_i+po, ln1_b_i+po, xnr,xni);
        // QKV: w = xn @ Wqkv^T
        cgemm_nt_kernel<0,false><<<dim3(8,16,1),256,SMEM_BYTES>>>(
            xnr,xni,DIM, qkv_w_r+wo,qkv_w_i+wo,DIM, wr,wi,DIM, DIM, 1.0f,
            0,0,0,0,0,0, nullptr,nullptr, nullptr,nullptr, nullptr,nullptr, 0);
        // dots[b,h] = scale * w @ conj(w)^T  (K=64)
        cgemm_nt_kernel<0,true><<<dim3(8,4,32),256,SMEM_BYTES>>>(
            wr,wi,DIM, wr,wi,DIM, dr,di,NN, DH, ATT_SCALE,
            sRow,(size_t)DH, sRow,(size_t)DH, (size_t)8*sNN, sNN,
            nullptr,nullptr, nullptr,nullptr, nullptr,nullptr, 0);
        // magnitude softmax (warp per row)
        csoftmax_kernel<<<BB*HEADS*NN/8,256>>>(dr,di);
        // att = attn @ w
        cgemm_nn_kernel<<<dim3(1,4,32),256,SMEM_BYTES>>>(
            dr,di,NN, wr,wi,DIM, ar,ai,DIM, NN,
            (size_t)8*sNN, sNN, sRow,(size_t)DH, sRow,(size_t)DH);
        // x = att @ Wout^T + bout + x
        cgemm_nt_kernel<1,false><<<dim3(8,16,1),256,SMEM_BYTES>>>(
            ar,ai,DIM, out_w_r+wo,out_w_i+wo,DIM, xr,xi,DIM, DIM, 1.0f,
            0,0,0,0,0,0, out_b_r+po,out_b_i+po, nullptr,nullptr, nullptr,nullptr, 0);
        // LN2
        cln_kernel<<<ROWS,128>>>(xr,xi, ln2_g_r+po, ln2_b_r+po, ln2_g_i+po, ln2_b_i+po, xnr,xni);
        // x = crelu(xn + ss*(xn @ Wff^T) - ss*lm)
        cgemm_nt_kernel<2,false><<<dim3(8,16,1),256,SMEM_BYTES>>>(
            xnr,xni,DIM, ff_w_r+wo,ff_w_i+wo,DIM, xr,xi,DIM, DIM, 1.0f,
            0,0,0,0,0,0, nullptr,nullptr, xnr,xni, step_sz,lambd, l);
    }

    copy_out_kernel<<<(NE+255)/256, 256>>>(xr, xi, (float*)d_out, NE);
}